// round 14
// baseline (speedup 1.0000x reference)
#include <cuda_runtime.h>
#include <cuda_fp16.h>
#include <math.h>
#include <float.h>
#include <stdint.h>

// Problem constants
#define NN    20000
#define EE    100000
#define GG    16
#define ET    (EE + NN)      // edges incl. self loops = 120000
#define TILE_ 32
#define EMB   128
#define HID   256
#define OUTC  512
#define HEADS 8
#define FEAT  512
#define HC1   (HEADS * HID)  // 2048
#define SLOPE 0.2f

// ---------------- scratch (static device globals; no runtime alloc) --------
__device__ __half g_hout[(size_t)NN * FEAT];  // layer3 fp16 out (pool input)
__device__ __half g_hlin[(size_t)NN * HC1];   // h_lin (GEMM output, fp16)
__device__ float g_scores[2 * NN * HEADS];    // esrc | edst
__device__ float g_pool[GG * FEAT];
__device__ float g_cnt [GG];
// fp16 operands for tensor-core GEMMs
__device__ __half g_A [(size_t)NN * HC1];
__device__ __half g_B [(size_t)HC1 * HC1];    // weight^T fp16 [N,K]
// CSR (by destination)
__device__ int g_rowptr[NN + 1];
__device__ int g_deg[NN];
__device__ int g_cursor[NN];
__device__ int g_eids[ET];

__device__ __forceinline__ float lrelu(float v) { return v > 0.f ? v : SLOPE * v; }

__device__ __forceinline__ void get_edge(const int* __restrict__ ei, int eid, int& s, int& d) {
    if (eid < EE) { s = ei[eid]; d = ei[EE + eid]; }
    else          { s = d = eid - EE; }
}

__device__ __forceinline__ uint32_t smem_u32(const void* p) {
    uint32_t a;
    asm("{ .reg .u64 t; cvta.to.shared.u64 t, %1; cvt.u32.u64 %0, t; }" : "=r"(a) : "l"(p));
    return a;
}

// ---------------- fills ------------------------------------------------------
__global__ void fillk(float* p, float v, size_t n) {
    size_t i = (size_t)blockIdx.x * blockDim.x + threadIdx.x;
    size_t stride = (size_t)gridDim.x * blockDim.x;
    for (; i < n; i += stride) p[i] = v;
}
__global__ void filli(int* p, int v, int n) {
    int i = blockIdx.x * blockDim.x + threadIdx.x;
    if (i < n) p[i] = v;
}

// ---------------- CSR build --------------------------------------------------
__global__ void count_deg(const int* __restrict__ ei, int* __restrict__ deg) {
    int eid = blockIdx.x * blockDim.x + threadIdx.x;
    if (eid >= ET) return;
    int s, d; get_edge(ei, eid, s, d);
    atomicAdd(&deg[d], 1);
}

__global__ void scan_rowptr(const int* __restrict__ deg, int* __restrict__ rowptr,
                            int* __restrict__ cursor) {
    __shared__ int buf[1024];
    __shared__ int carry;
    int tid = threadIdx.x;
    if (tid == 0) carry = 0;
    __syncthreads();
    for (int base = 0; base < NN; base += 1024) {
        int i = base + tid;
        int v = (i < NN) ? deg[i] : 0;
        buf[tid] = v;
        __syncthreads();
        for (int off = 1; off < 1024; off <<= 1) {
            int t = (tid >= off) ? buf[tid - off] : 0;
            __syncthreads();
            buf[tid] += t;
            __syncthreads();
        }
        if (i < NN) {
            int inc = carry + buf[tid];
            rowptr[i + 1] = inc;
            cursor[i] = inc - v;
        }
        __syncthreads();
        if (tid == 0) carry += buf[1023];
        __syncthreads();
    }
    if (tid == 0) rowptr[0] = 0;
}

__global__ void scatter_edges(const int* __restrict__ ei, int* __restrict__ cur,
                              int* __restrict__ eids) {
    int eid = blockIdx.x * blockDim.x + threadIdx.x;
    if (eid >= ET) return;
    int s, d; get_edge(ei, eid, s, d);
    int pos = atomicAdd(&cur[d], 1);
    eids[pos] = eid;
}

// =================== weight transpose to fp16 ================================
__global__ void tconv_t(const float* __restrict__ W, __half* __restrict__ o,
                        int K, int N) {
    __shared__ float t[32][33];
    int kb = blockIdx.y * 32, nb = blockIdx.x * 32;
    int tx = threadIdx.x, ty = threadIdx.y;
    #pragma unroll
    for (int i = ty; i < 32; i += 8)
        t[i][tx] = W[(size_t)(kb + i) * N + nb + tx];
    __syncthreads();
    #pragma unroll
    for (int i = ty; i < 32; i += 8)
        o[(size_t)(nb + i) * K + kb + tx] = __float2half_rn(t[tx][i]);
}

// =================== warp-MMA fp16 GEMM (K-chunk 64) =========================
// CTA tile 128x128, 8 warps (2x4), warp tile 64x32, K-chunk 64, 3-stage
// cp.async pipeline, 2 CTAs/SM. Smem rows stride 72 fp16 (144B, conflict-free).
#define WG_STRIDE  72
#define WG_T       (128 * WG_STRIDE * 2)   // 18432 B per 128x64 fp16 tile
#define WG_STAGE   (2 * WG_T)              // A, B = 36864
#define WG_STAGES  3
#define WG_SMEM    (WG_STAGES * WG_STAGE)  // 110592

__device__ __forceinline__ void lda4(uint32_t addr, uint32_t* r) {
    asm volatile("ldmatrix.sync.aligned.m8n8.x4.shared.b16 {%0,%1,%2,%3}, [%4];"
                 : "=r"(r[0]), "=r"(r[1]), "=r"(r[2]), "=r"(r[3]) : "r"(addr));
}

__device__ __forceinline__ void mma16816(float* d, const uint32_t* a, const uint32_t* b) {
    asm volatile("mma.sync.aligned.m16n8k16.row.col.f32.f16.f16.f32 "
                 "{%0,%1,%2,%3}, {%4,%5,%6,%7}, {%8,%9}, {%0,%1,%2,%3};"
                 : "+f"(d[0]), "+f"(d[1]), "+f"(d[2]), "+f"(d[3])
                 : "r"(a[0]), "r"(a[1]), "r"(a[2]), "r"(a[3]), "r"(b[0]), "r"(b[1]));
}

__global__ void __launch_bounds__(256, 2)
wgemm(const __half* __restrict__ A, const __half* __restrict__ B,
      __half* __restrict__ C, int M, int Ntot, int Ktot,
      const float* __restrict__ a_s, const float* __restrict__ a_d,
      float* __restrict__ esrc, float* __restrict__ edst, int H, int Cc)
{
    extern __shared__ char sm_[];
    const uint32_t smb = smem_u32(sm_);
    const int tid = threadIdx.x;
    const int lane = tid & 31, wid = tid >> 5;
    const int wm = wid & 1;          // 0..1 (64 rows each)
    const int wn = wid >> 1;         // 0..3 (32 cols each)
    const int m0 = blockIdx.y * 128;
    const int n0 = blockIdx.x * 128;
    const int NC = Ktot / 64;

    float acc[4][4][4];
    #pragma unroll
    for (int i = 0; i < 4; i++)
        #pragma unroll
        for (int j = 0; j < 4; j++)
            #pragma unroll
            for (int q = 0; q < 4; q++) acc[i][j][q] = 0.f;

    const int arow  = wm * 64 + (lane & 15);
    const int acolh = (lane >> 4) << 3;
    const int brow  = wn * 32 + (lane & 7) + ((lane >> 4) << 3);
    const int bcol  = lane & 8;

    auto load_stage = [&](int c, int st) {
        const int k0 = c * 64;
        const uint32_t sb = smb + st * WG_STAGE;
        #pragma unroll
        for (int i = 0; i < 4; i++) {
            int idx = tid + i * 256;
            int row = idx >> 3;
            int seg = idx & 7;
            int gr = m0 + row;
            int ok = gr < M;
            const __half* g = A + (size_t)(ok ? gr : 0) * Ktot + k0 + seg * 8;
            uint32_t dst = sb + row * (WG_STRIDE * 2) + seg * 16;
            int sz = ok ? 16 : 0;
            asm volatile("cp.async.cg.shared.global [%0], [%1], 16, %2;"
                         :: "r"(dst), "l"(g), "r"(sz));
        }
        #pragma unroll
        for (int i = 0; i < 4; i++) {
            int idx = tid + i * 256;
            int row = idx >> 3;
            int seg = idx & 7;
            const __half* g = B + (size_t)(n0 + row) * Ktot + k0 + seg * 8;
            uint32_t dst = sb + WG_T + row * (WG_STRIDE * 2) + seg * 16;
            asm volatile("cp.async.cg.shared.global [%0], [%1], 16, %2;"
                         :: "r"(dst), "l"(g), "r"(16));
        }
        asm volatile("cp.async.commit_group;" ::: "memory");
    };

    load_stage(0, 0);
    if (NC > 1) load_stage(1, 1);

    for (int c = 0; c < NC; c++) {
        if (c + 1 < NC) {
            asm volatile("cp.async.wait_group 1;" ::: "memory");
        } else {
            asm volatile("cp.async.wait_group 0;" ::: "memory");
        }
        __syncthreads();
        if (c + 2 < NC) load_stage(c + 2, (c + 2) % WG_STAGES);

        const uint32_t sb = smb + (c % WG_STAGES) * WG_STAGE;
        #pragma unroll
        for (int ks = 0; ks < 4; ks++) {
            uint32_t aH[4][4], bH[4][2];
            #pragma unroll
            for (int i = 0; i < 4; i++) {
                uint32_t off = (uint32_t)((arow + i * 16) * (WG_STRIDE * 2) +
                                          (ks * 16 + acolh) * 2);
                lda4(sb + off, aH[i]);
            }
            #pragma unroll
            for (int jp = 0; jp < 2; jp++) {
                uint32_t off = (uint32_t)((brow + jp * 16) * (WG_STRIDE * 2) +
                                          (ks * 16 + bcol) * 2);
                uint32_t t[4];
                lda4(sb + WG_T + off, t);
                bH[jp * 2][0] = t[0]; bH[jp * 2][1] = t[1];
                bH[jp * 2 + 1][0] = t[2]; bH[jp * 2 + 1][1] = t[3];
            }
            #pragma unroll
            for (int i = 0; i < 4; i++)
                #pragma unroll
                for (int j = 0; j < 4; j++)
                    mma16816(acc[i][j], aH[i], bH[j]);
        }
        __syncthreads();
    }

    // ---- fused attention-score epilogue ----
    {
        float* sAs = (float*)sm_;
        float* sAd = sAs + 128;
        if (tid < 128) { sAs[tid] = a_s[n0 + tid]; sAd[tid] = a_d[n0 + tid]; }
        __syncthreads();
        const int hh = n0 / Cc;
        #pragma unroll
        for (int i = 0; i < 4; i++) {
            float slo = 0.f, shi = 0.f, dlo = 0.f, dhi = 0.f;
            #pragma unroll
            for (int j = 0; j < 4; j++) {
                int cc = wn * 32 + j * 8 + 2 * (lane & 3);
                float A0 = sAs[cc], A1 = sAs[cc + 1];
                float D0 = sAd[cc], D1 = sAd[cc + 1];
                slo += acc[i][j][0] * A0 + acc[i][j][1] * A1;
                shi += acc[i][j][2] * A0 + acc[i][j][3] * A1;
                dlo += acc[i][j][0] * D0 + acc[i][j][1] * D1;
                dhi += acc[i][j][2] * D0 + acc[i][j][3] * D1;
            }
            #pragma unroll
            for (int o = 1; o < 4; o <<= 1) {
                slo += __shfl_xor_sync(0xFFFFFFFFu, slo, o);
                shi += __shfl_xor_sync(0xFFFFFFFFu, shi, o);
                dlo += __shfl_xor_sync(0xFFFFFFFFu, dlo, o);
                dhi += __shfl_xor_sync(0xFFFFFFFFu, dhi, o);
            }
            if ((lane & 3) == 0) {
                int r0 = m0 + wm * 64 + i * 16 + (lane >> 2);
                if (r0 < M) {
                    atomicAdd(&esrc[r0 * H + hh], slo);
                    atomicAdd(&edst[r0 * H + hh], dlo);
                }
                if (r0 + 8 < M) {
                    atomicAdd(&esrc[(r0 + 8) * H + hh], shi);
                    atomicAdd(&edst[(r0 + 8) * H + hh], dhi);
                }
            }
        }
    }

    // ---- C stores (fp16) ----
    #pragma unroll
    for (int i = 0; i < 4; i++) {
        int r0 = m0 + wm * 64 + i * 16 + (lane >> 2);
        #pragma unroll
        for (int j = 0; j < 4; j++) {
            int col = n0 + wn * 32 + j * 8 + 2 * (lane & 3);
            if (r0 < M)
                *(__half2*)(C + (size_t)r0 * Ntot + col) =
                    __floats2half2_rn(acc[i][j][0], acc[i][j][1]);
            if (r0 + 8 < M)
                *(__half2*)(C + (size_t)(r0 + 8) * Ntot + col) =
                    __floats2half2_rn(acc[i][j][2], acc[i][j][3]);
        }
    }
}

// ---------------- SIMT SGEMM (layer0 only) — writes fp16 A ------------------
__global__ void __launch_bounds__(256)
sgemm0(const float* __restrict__ A, const float* __restrict__ B,
       __half* __restrict__ outA,
       int M, int N, int K, const float* __restrict__ bias)
{
    __shared__ float As[16][128];
    __shared__ float Bs[16][128];
    const int tid = threadIdx.x;
    const int m0 = blockIdx.y * 128;
    const int n0 = blockIdx.x * 128;
    const int tr = (tid >> 4) << 3;
    const int tc = (tid & 15) << 3;

    float acc[8][8];
    #pragma unroll
    for (int i = 0; i < 8; i++)
        #pragma unroll
        for (int j = 0; j < 8; j++) acc[i][j] = 0.f;

    for (int k0 = 0; k0 < K; k0 += 16) {
        #pragma unroll
        for (int it = 0; it < 2; it++) {
            int idx = tid + it * 256;
            int row = idx >> 2;
            int c4  = (idx & 3) << 2;
            float4 v = make_float4(0.f, 0.f, 0.f, 0.f);
            int gr = m0 + row;
            if (gr < M) v = *(const float4*)(A + (size_t)gr * K + k0 + c4);
            As[c4 + 0][row] = v.x;
            As[c4 + 1][row] = v.y;
            As[c4 + 2][row] = v.z;
            As[c4 + 3][row] = v.w;
        }
        #pragma unroll
        for (int it = 0; it < 2; it++) {
            int idx = tid + it * 256;
            int row = idx >> 5;
            int c4  = (idx & 31) << 2;
            float4 v = *(const float4*)(B + (size_t)(k0 + row) * N + n0 + c4);
            *(float4*)&Bs[row][c4] = v;
        }
        __syncthreads();
        #pragma unroll
        for (int k = 0; k < 16; k++) {
            float a[8], b[8];
            #pragma unroll
            for (int i = 0; i < 8; i++) a[i] = As[k][tr + i];
            #pragma unroll
            for (int j = 0; j < 8; j++) b[j] = Bs[k][tc + j];
            #pragma unroll
            for (int i = 0; i < 8; i++)
                #pragma unroll
                for (int j = 0; j < 8; j++)
                    acc[i][j] = fmaf(a[i], b[j], acc[i][j]);
        }
        __syncthreads();
    }

    #pragma unroll
    for (int i = 0; i < 8; i++) {
        int gr = m0 + tr + i;
        if (gr >= M) break;
        #pragma unroll
        for (int j = 0; j < 8; j += 2) {
            float v0 = lrelu(acc[i][j + 0] + bias[n0 + tc + j + 0]);
            float v1 = lrelu(acc[i][j + 1] + bias[n0 + tc + j + 1]);
            size_t o = (size_t)gr * N + n0 + tc + j;
            *(__half2*)(outA + o) = __floats2half2_rn(v0, v1);
        }
    }
}

// ---------------- gather with fused softmax (warp per dst,256-col chunk) ----
__global__ void __launch_bounds__(256)
gat_gather(const int* __restrict__ rowptr, const int* __restrict__ eids,
           const int* __restrict__ ei,
           const __half* __restrict__ hlin,
           const float* __restrict__ esrc, const float* __restrict__ edst,
           const float* __restrict__ bias,
           __half* __restrict__ outA,
           int H, int HC, int cshift)
{
    const int w = blockIdx.x * 8 + (threadIdx.x >> 5);
    const int lane = threadIdx.x & 31;
    const int d = w % NN;
    const int chunk = w / NN;
    const int c = chunk * 256 + lane * 8;
    const int h = (chunk * 256) >> cshift;      // warp-uniform head
    const int r0 = rowptr[d], r1 = rowptr[d + 1];
    const float ed = edst[d * H + h];

    // ---- pass 1: per-edge scores, warp max ----
    float mx = -FLT_MAX;
    for (int e0 = r0; e0 < r1; e0 += 32) {
        int e = e0 + lane;
        if (e < r1) {
            int eid = eids[e]; int s, dd; get_edge(ei, eid, s, dd);
            mx = fmaxf(mx, lrelu(esrc[s * H + h] + ed));
        }
    }
    #pragma unroll
    for (int o = 16; o > 0; o >>= 1)
        mx = fmaxf(mx, __shfl_xor_sync(0xFFFFFFFFu, mx, o));

    // ---- pass 2: warp sum of exp ----
    float sm = 0.f;
    for (int e0 = r0; e0 < r1; e0 += 32) {
        int e = e0 + lane;
        if (e < r1) {
            int eid = eids[e]; int s, dd; get_edge(ei, eid, s, dd);
            sm += __expf(lrelu(esrc[s * H + h] + ed) - mx);
        }
    }
    #pragma unroll
    for (int o = 16; o > 0; o >>= 1)
        sm += __shfl_xor_sync(0xFFFFFFFFu, sm, o);
    const float inv = 1.0f / (sm + 1e-16f);

    // ---- pass 3: weighted gather ----
    float acc[8];
    #pragma unroll
    for (int q = 0; q < 8; q++) acc[q] = 0.f;

    for (int e0 = r0; e0 < r1; e0 += 32) {
        int e = e0 + lane;
        int mys = 0; float mya = 0.f;
        if (e < r1) {
            int eid = eids[e]; int s, dd; get_edge(ei, eid, s, dd);
            mys = s;
            mya = __expf(lrelu(esrc[s * H + h] + ed) - mx) * inv;
        }
        int cnt = min(32, r1 - e0);
        int j = 0;
        for (; j + 1 < cnt; j += 2) {
            int s0 = __shfl_sync(0xFFFFFFFFu, mys, j);
            int s1 = __shfl_sync(0xFFFFFFFFu, mys, j + 1);
            float a0 = __shfl_sync(0xFFFFFFFFu, mya, j);
            float a1 = __shfl_sync(0xFFFFFFFFu, mya, j + 1);
            uint4 r0v = *(const uint4*)(hlin + (size_t)s0 * HC + c);
            uint4 r1v = *(const uint4*)(hlin + (size_t)s1 * HC + c);
            const __half2* h0 = (const __half2*)&r0v;
            const __half2* h1 = (const __half2*)&r1v;
            #pragma unroll
            for (int q = 0; q < 4; q++) {
                float2 f0 = __half22float2(h0[q]);
                float2 f1 = __half22float2(h1[q]);
                acc[q * 2 + 0] = fmaf(a0, f0.x, fmaf(a1, f1.x, acc[q * 2 + 0]));
                acc[q * 2 + 1] = fmaf(a0, f0.y, fmaf(a1, f1.y, acc[q * 2 + 1]));
            }
        }
        if (j < cnt) {
            int s0 = __shfl_sync(0xFFFFFFFFu, mys, j);
            float a0 = __shfl_sync(0xFFFFFFFFu, mya, j);
            uint4 raw = *(const uint4*)(hlin + (size_t)s0 * HC + c);
            const __half2* hp = (const __half2*)&raw;
            #pragma unroll
            for (int q = 0; q < 4; q++) {
                float2 f = __half22float2(hp[q]);
                acc[q * 2 + 0] = fmaf(a0, f.x, acc[q * 2 + 0]);
                acc[q * 2 + 1] = fmaf(a0, f.y, acc[q * 2 + 1]);
            }
        }
    }

    __half2 hx[4];
    #pragma unroll
    for (int q = 0; q < 4; q++) {
        float v0 = lrelu(acc[q * 2 + 0] + bias[c + q * 2 + 0]);
        float v1 = lrelu(acc[q * 2 + 1] + bias[c + q * 2 + 1]);
        hx[q] = __floats2half2_rn(v0, v1);
    }
    *(uint4*)(outA + (size_t)d * HC + c) = *(uint4*)hx;
}

// ---------------- pooling (sorted-batch run accumulation, fp16 input) -------
__global__ void pool2(const __half* __restrict__ h, const int* __restrict__ batch,
                      float* __restrict__ pool, float* __restrict__ cnt) {
    __shared__ int bid[128];
    int base = blockIdx.x * 128;
    int tid = threadIdx.x;
    for (int i = tid; i < 128; i += 256)
        bid[i] = (base + i < NN) ? batch[base + i] : -1;
    __syncthreads();
    int c = tid;
    float a0 = 0.f, a1 = 0.f;
    int rl = 0;
    int cur = bid[0];
    for (int i = 0; i < 128; i++) {
        int g = bid[i];
        if (g < 0) break;
        if (g != cur) {
            atomicAdd(&pool[cur * FEAT + c], a0);
            atomicAdd(&pool[cur * FEAT + c + 256], a1);
            if (tid == 0) atomicAdd(&cnt[cur], (float)rl);
            a0 = a1 = 0.f;
            rl = 0;
            cur = g;
        }
        const __half* row = h + (size_t)(base + i) * FEAT;
        a0 += __half2float(row[c]);
        a1 += __half2float(row[c + 256]);
        rl++;
    }
    if (cur >= 0) {
        atomicAdd(&pool[cur * FEAT + c], a0);
        atomicAdd(&pool[cur * FEAT + c + 256], a1);
        if (tid == 0) atomicAdd(&cnt[cur], (float)rl);
    }
}

__global__ void final_mlp(const float* __restrict__ pool, const float* __restrict__ cnt,
                          const float* __restrict__ Wf, const float* __restrict__ bf,
                          float* __restrict__ out)
{
    int g = blockIdx.x;
    int o = threadIdx.x;
    float inv = 1.0f / fmaxf(cnt[g], 1.0f);
    float acc = bf[o];
    const float* pg = pool + g * FEAT;
    #pragma unroll 8
    for (int k = 0; k < FEAT; k++)
        acc = fmaf(pg[k] * inv, Wf[k * FEAT + o], acc);
    out[g * FEAT + o] = lrelu(acc);
}

// ---------------- host orchestration ----------------------------------------
struct Ptrs {
    float *scores, *pool, *cnt;
    __half *hout, *hlin, *A, *B;
    int *rowptr, *deg, *cursor, *eids;
};

extern "C" void kernel_launch(void* const* d_in, const int* in_sizes, int n_in,
                              void* d_out, int out_size)
{
    const float* x     = (const float*)d_in[0];
    const int*   ei    = (const int*)  d_in[1];
    const int*   batch = (const int*)  d_in[2];
    const float* W0  = (const float*)d_in[3];
    const float* b0  = (const float*)d_in[4];
    const float* W1  = (const float*)d_in[5];
    const float* a1s = (const float*)d_in[6];
    const float* a1d = (const float*)d_in[7];
    const float* b1  = (const float*)d_in[8];
    const float* W2  = (const float*)d_in[9];
    const float* a2s = (const float*)d_in[10];
    const float* a2d = (const float*)d_in[11];
    const float* b2  = (const float*)d_in[12];
    const float* W3  = (const float*)d_in[13];
    const float* a3s = (const float*)d_in[14];
    const float* a3d = (const float*)d_in[15];
    const float* b3  = (const float*)d_in[16];
    const float* Wf  = (const float*)d_in[17];
    const float* bf  = (const float*)d_in[18];
    float* out = (float*)d_out;

    cudaFuncSetAttribute(wgemm, cudaFuncAttributeMaxDynamicSharedMemorySize, WG_SMEM);

    Ptrs P;
    cudaGetSymbolAddress((void**)&P.hout,   g_hout);
    cudaGetSymbolAddress((void**)&P.hlin,   g_hlin);
    cudaGetSymbolAddress((void**)&P.scores, g_scores);
    cudaGetSymbolAddress((void**)&P.pool,   g_pool);
    cudaGetSymbolAddress((void**)&P.cnt,    g_cnt);
    cudaGetSymbolAddress((void**)&P.A,      g_A);
    cudaGetSymbolAddress((void**)&P.B,      g_B);
    cudaGetSymbolAddress((void**)&P.rowptr, g_rowptr);
    cudaGetSymbolAddress((void**)&P.deg,    g_deg);
    cudaGetSymbolAddress((void**)&P.cursor, g_cursor);
    cudaGetSymbolAddress((void**)&P.eids,   g_eids);

    float* esrc = P.scores;
    float* edst = P.scores + NN * HEADS;

    const float* Ws[3]  = { W1, W2, W3 };
    const float* ass[3] = { a1s, a2s, a3s };
    const float* ads[3] = { a1d, a2d, a3d };
    const float* bs[3]  = { b1, b2, b3 };
    const int Kin[3]    = { EMB, HC1, HC1 };
    const int Hs[3]     = { HEADS, HEADS, 1 };
    const int Cs[3]     = { HID, HID, OUTC };
    const int cshifts[3]= { 8, 8, 9 };

    // 1: layer0 GEMM (writes fp16 A directly)
    {
        dim3 g0(EMB / 128, (NN + 127) / 128);
        sgemm0<<<g0, 256>>>(x, W0, P.A, NN, EMB, TILE_, b0);
    }
    // 2: weight convert for layer 1
    {
        dim3 tb(32, 8), tg(HC1 / 32, EMB / 32);
        tconv_t<<<tg, tb>>>(W1, P.B, EMB, HC1);
    }
    // 3: zero scores
    fillk<<<64, 256>>>(P.scores, 0.f, (size_t)2 * NN * HEADS);
    // 4: wgemm layer 1  <-- ncu capture slot
    {
        dim3 gg(HC1 / 128, (NN + 127) / 128);
        wgemm<<<gg, 256, WG_SMEM>>>(P.A, P.B, P.hlin, NN, HC1, EMB,
                                    a1s, a1d, esrc, edst, HEADS, HID);
    }
    // CSR build
    filli<<<(NN + 255) / 256, 256>>>(P.deg, 0, NN);
    count_deg<<<(ET + 255) / 256, 256>>>(ei, P.deg);
    scan_rowptr<<<1, 1024>>>(P.deg, P.rowptr, P.cursor);
    scatter_edges<<<(ET + 255) / 256, 256>>>(ei, P.cursor, P.eids);

    for (int L = 0; L < 3; L++) {
        int H = Hs[L], C = Cs[L], HC = H * C;
        if (L > 0) {
            dim3 tb(32, 8), tg(HC / 32, Kin[L] / 32);
            tconv_t<<<tg, tb>>>(Ws[L], P.B, Kin[L], HC);
            fillk<<<64, 256>>>(P.scores, 0.f, (size_t)2 * NN * HEADS);
            dim3 gg(HC / 128, (NN + 127) / 128);
            wgemm<<<gg, 256, WG_SMEM>>>(P.A, P.B, P.hlin, NN, HC, Kin[L],
                                        ass[L], ads[L], esrc, edst, H, C);
        }
        int nchunks = HC / 256;
        int nwarps = NN * nchunks;
        __half* dstA = (L == 2) ? P.hout : P.A;
        gat_gather<<<nwarps / 8, 256>>>(P.rowptr, P.eids, ei, P.hlin, esrc, edst,
                                        bs[L], dstA, H, HC, cshifts[L]);
    }

    // ---- global mean pool + final MLP ----
    fillk<<<32, 256>>>(P.pool, 0.f, (size_t)GG * FEAT);
    fillk<<<1, 32>>>(P.cnt, 0.f, (size_t)GG);
    pool2<<<(NN + 127) / 128, 256>>>(P.hout, batch, P.pool, P.cnt);
    final_mlp<<<GG, FEAT>>>(P.pool, P.cnt, Wf, bf, out);
}

// round 15
// speedup vs baseline: 1.0030x; 1.0030x over previous
#include <cuda_runtime.h>
#include <cuda_fp16.h>
#include <math.h>
#include <float.h>
#include <stdint.h>

// Problem constants
#define NN    20000
#define EE    100000
#define GG    16
#define ET    (EE + NN)      // edges incl. self loops = 120000
#define TILE_ 32
#define EMB   128
#define HID   256
#define OUTC  512
#define HEADS 8
#define FEAT  512
#define HC1   (HEADS * HID)  // 2048
#define SLOPE 0.2f

// ---------------- scratch (static device globals; no runtime alloc) --------
__device__ __half g_hout[(size_t)NN * FEAT];  // layer3 fp16 out (pool input)
__device__ __half g_hlin[(size_t)NN * HC1];   // h_lin (GEMM output, fp16)
__device__ float g_scores[2 * NN * HEADS];    // esrc | edst
__device__ float g_pool[GG * FEAT];
__device__ float g_cnt [GG];
// fp16 operands for tensor-core GEMMs
__device__ __half g_A [(size_t)NN * HC1];
__device__ __half g_B [(size_t)HC1 * HC1];    // weight^T fp16 [N,K]
// CSR (by destination)
__device__ int g_rowptr[NN + 1];
__device__ int g_deg[NN];
__device__ int g_cursor[NN];
__device__ int g_eids[ET];

__device__ __forceinline__ float lrelu(float v) { return v > 0.f ? v : SLOPE * v; }

__device__ __forceinline__ void get_edge(const int* __restrict__ ei, int eid, int& s, int& d) {
    if (eid < EE) { s = ei[eid]; d = ei[EE + eid]; }
    else          { s = d = eid - EE; }
}

__device__ __forceinline__ uint32_t smem_u32(const void* p) {
    uint32_t a;
    asm("{ .reg .u64 t; cvta.to.shared.u64 t, %1; cvt.u32.u64 %0, t; }" : "=r"(a) : "l"(p));
    return a;
}

// ---------------- fills ------------------------------------------------------
__global__ void fillk(float* p, float v, size_t n) {
    size_t i = (size_t)blockIdx.x * blockDim.x + threadIdx.x;
    size_t stride = (size_t)gridDim.x * blockDim.x;
    for (; i < n; i += stride) p[i] = v;
}
__global__ void filli(int* p, int v, int n) {
    int i = blockIdx.x * blockDim.x + threadIdx.x;
    if (i < n) p[i] = v;
}

// ---------------- CSR build --------------------------------------------------
__global__ void count_deg(const int* __restrict__ ei, int* __restrict__ deg) {
    int eid = blockIdx.x * blockDim.x + threadIdx.x;
    if (eid >= ET) return;
    int s, d; get_edge(ei, eid, s, d);
    atomicAdd(&deg[d], 1);
}

__global__ void scan_rowptr(const int* __restrict__ deg, int* __restrict__ rowptr,
                            int* __restrict__ cursor) {
    __shared__ int buf[1024];
    __shared__ int carry;
    int tid = threadIdx.x;
    if (tid == 0) carry = 0;
    __syncthreads();
    for (int base = 0; base < NN; base += 1024) {
        int i = base + tid;
        int v = (i < NN) ? deg[i] : 0;
        buf[tid] = v;
        __syncthreads();
        for (int off = 1; off < 1024; off <<= 1) {
            int t = (tid >= off) ? buf[tid - off] : 0;
            __syncthreads();
            buf[tid] += t;
            __syncthreads();
        }
        if (i < NN) {
            int inc = carry + buf[tid];
            rowptr[i + 1] = inc;
            cursor[i] = inc - v;
        }
        __syncthreads();
        if (tid == 0) carry += buf[1023];
        __syncthreads();
    }
    if (tid == 0) rowptr[0] = 0;
}

__global__ void scatter_edges(const int* __restrict__ ei, int* __restrict__ cur,
                              int* __restrict__ eids) {
    int eid = blockIdx.x * blockDim.x + threadIdx.x;
    if (eid >= ET) return;
    int s, d; get_edge(ei, eid, s, d);
    int pos = atomicAdd(&cur[d], 1);
    eids[pos] = eid;
}

// =================== weight transpose to fp16 ================================
__global__ void tconv_t(const float* __restrict__ W, __half* __restrict__ o,
                        int K, int N) {
    __shared__ float t[32][33];
    int kb = blockIdx.y * 32, nb = blockIdx.x * 32;
    int tx = threadIdx.x, ty = threadIdx.y;
    #pragma unroll
    for (int i = ty; i < 32; i += 8)
        t[i][tx] = W[(size_t)(kb + i) * N + nb + tx];
    __syncthreads();
    #pragma unroll
    for (int i = ty; i < 32; i += 8)
        o[(size_t)(nb + i) * K + kb + tx] = __float2half_rn(t[tx][i]);
}

// =================== warp-MMA fp16 GEMM (K-chunk 64) =========================
// CTA tile 128x128, 8 warps (2x4), warp tile 64x32, K-chunk 64, 3-stage
// cp.async pipeline, 2 CTAs/SM. Smem rows stride 72 fp16 (144B, conflict-free).
#define WG_STRIDE  72
#define WG_T       (128 * WG_STRIDE * 2)   // 18432 B per 128x64 fp16 tile
#define WG_STAGE   (2 * WG_T)              // A, B = 36864
#define WG_STAGES  3
#define WG_SMEM    (WG_STAGES * WG_STAGE)  // 110592

__device__ __forceinline__ void lda4(uint32_t addr, uint32_t* r) {
    asm volatile("ldmatrix.sync.aligned.m8n8.x4.shared.b16 {%0,%1,%2,%3}, [%4];"
                 : "=r"(r[0]), "=r"(r[1]), "=r"(r[2]), "=r"(r[3]) : "r"(addr));
}

__device__ __forceinline__ void mma16816(float* d, const uint32_t* a, const uint32_t* b) {
    asm volatile("mma.sync.aligned.m16n8k16.row.col.f32.f16.f16.f32 "
                 "{%0,%1,%2,%3}, {%4,%5,%6,%7}, {%8,%9}, {%0,%1,%2,%3};"
                 : "+f"(d[0]), "+f"(d[1]), "+f"(d[2]), "+f"(d[3])
                 : "r"(a[0]), "r"(a[1]), "r"(a[2]), "r"(a[3]), "r"(b[0]), "r"(b[1]));
}

__global__ void __launch_bounds__(256, 2)
wgemm(const __half* __restrict__ A, const __half* __restrict__ B,
      __half* __restrict__ C, int M, int Ntot, int Ktot,
      const float* __restrict__ a_s, const float* __restrict__ a_d,
      float* __restrict__ esrc, float* __restrict__ edst, int H, int Cc)
{
    extern __shared__ char sm_[];
    const uint32_t smb = smem_u32(sm_);
    const int tid = threadIdx.x;
    const int lane = tid & 31, wid = tid >> 5;
    const int wm = wid & 1;          // 0..1 (64 rows each)
    const int wn = wid >> 1;         // 0..3 (32 cols each)
    const int m0 = blockIdx.y * 128;
    const int n0 = blockIdx.x * 128;
    const int NC = Ktot / 64;

    float acc[4][4][4];
    #pragma unroll
    for (int i = 0; i < 4; i++)
        #pragma unroll
        for (int j = 0; j < 4; j++)
            #pragma unroll
            for (int q = 0; q < 4; q++) acc[i][j][q] = 0.f;

    const int arow  = wm * 64 + (lane & 15);
    const int acolh = (lane >> 4) << 3;
    const int brow  = wn * 32 + (lane & 7) + ((lane >> 4) << 3);
    const int bcol  = lane & 8;

    auto load_stage = [&](int c, int st) {
        const int k0 = c * 64;
        const uint32_t sb = smb + st * WG_STAGE;
        #pragma unroll
        for (int i = 0; i < 4; i++) {
            int idx = tid + i * 256;
            int row = idx >> 3;
            int seg = idx & 7;
            int gr = m0 + row;
            int ok = gr < M;
            const __half* g = A + (size_t)(ok ? gr : 0) * Ktot + k0 + seg * 8;
            uint32_t dst = sb + row * (WG_STRIDE * 2) + seg * 16;
            int sz = ok ? 16 : 0;
            asm volatile("cp.async.cg.shared.global [%0], [%1], 16, %2;"
                         :: "r"(dst), "l"(g), "r"(sz));
        }
        #pragma unroll
        for (int i = 0; i < 4; i++) {
            int idx = tid + i * 256;
            int row = idx >> 3;
            int seg = idx & 7;
            const __half* g = B + (size_t)(n0 + row) * Ktot + k0 + seg * 8;
            uint32_t dst = sb + WG_T + row * (WG_STRIDE * 2) + seg * 16;
            asm volatile("cp.async.cg.shared.global [%0], [%1], 16, %2;"
                         :: "r"(dst), "l"(g), "r"(16));
        }
        asm volatile("cp.async.commit_group;" ::: "memory");
    };

    load_stage(0, 0);
    if (NC > 1) load_stage(1, 1);

    for (int c = 0; c < NC; c++) {
        if (c + 1 < NC) {
            asm volatile("cp.async.wait_group 1;" ::: "memory");
        } else {
            asm volatile("cp.async.wait_group 0;" ::: "memory");
        }
        __syncthreads();
        if (c + 2 < NC) load_stage(c + 2, (c + 2) % WG_STAGES);

        const uint32_t sb = smb + (c % WG_STAGES) * WG_STAGE;
        #pragma unroll
        for (int ks = 0; ks < 4; ks++) {
            uint32_t aH[4][4], bH[4][2];
            #pragma unroll
            for (int i = 0; i < 4; i++) {
                uint32_t off = (uint32_t)((arow + i * 16) * (WG_STRIDE * 2) +
                                          (ks * 16 + acolh) * 2);
                lda4(sb + off, aH[i]);
            }
            #pragma unroll
            for (int jp = 0; jp < 2; jp++) {
                uint32_t off = (uint32_t)((brow + jp * 16) * (WG_STRIDE * 2) +
                                          (ks * 16 + bcol) * 2);
                uint32_t t[4];
                lda4(sb + WG_T + off, t);
                bH[jp * 2][0] = t[0]; bH[jp * 2][1] = t[1];
                bH[jp * 2 + 1][0] = t[2]; bH[jp * 2 + 1][1] = t[3];
            }
            #pragma unroll
            for (int i = 0; i < 4; i++)
                #pragma unroll
                for (int j = 0; j < 4; j++)
                    mma16816(acc[i][j], aH[i], bH[j]);
        }
        __syncthreads();
    }

    // ---- fused attention-score epilogue ----
    {
        float* sAs = (float*)sm_;
        float* sAd = sAs + 128;
        if (tid < 128) { sAs[tid] = a_s[n0 + tid]; sAd[tid] = a_d[n0 + tid]; }
        __syncthreads();
        const int hh = n0 / Cc;
        #pragma unroll
        for (int i = 0; i < 4; i++) {
            float slo = 0.f, shi = 0.f, dlo = 0.f, dhi = 0.f;
            #pragma unroll
            for (int j = 0; j < 4; j++) {
                int cc = wn * 32 + j * 8 + 2 * (lane & 3);
                float A0 = sAs[cc], A1 = sAs[cc + 1];
                float D0 = sAd[cc], D1 = sAd[cc + 1];
                slo += acc[i][j][0] * A0 + acc[i][j][1] * A1;
                shi += acc[i][j][2] * A0 + acc[i][j][3] * A1;
                dlo += acc[i][j][0] * D0 + acc[i][j][1] * D1;
                dhi += acc[i][j][2] * D0 + acc[i][j][3] * D1;
            }
            #pragma unroll
            for (int o = 1; o < 4; o <<= 1) {
                slo += __shfl_xor_sync(0xFFFFFFFFu, slo, o);
                shi += __shfl_xor_sync(0xFFFFFFFFu, shi, o);
                dlo += __shfl_xor_sync(0xFFFFFFFFu, dlo, o);
                dhi += __shfl_xor_sync(0xFFFFFFFFu, dhi, o);
            }
            if ((lane & 3) == 0) {
                int r0 = m0 + wm * 64 + i * 16 + (lane >> 2);
                if (r0 < M) {
                    atomicAdd(&esrc[r0 * H + hh], slo);
                    atomicAdd(&edst[r0 * H + hh], dlo);
                }
                if (r0 + 8 < M) {
                    atomicAdd(&esrc[(r0 + 8) * H + hh], shi);
                    atomicAdd(&edst[(r0 + 8) * H + hh], dhi);
                }
            }
        }
    }

    // ---- C stores (fp16) ----
    #pragma unroll
    for (int i = 0; i < 4; i++) {
        int r0 = m0 + wm * 64 + i * 16 + (lane >> 2);
        #pragma unroll
        for (int j = 0; j < 4; j++) {
            int col = n0 + wn * 32 + j * 8 + 2 * (lane & 3);
            if (r0 < M)
                *(__half2*)(C + (size_t)r0 * Ntot + col) =
                    __floats2half2_rn(acc[i][j][0], acc[i][j][1]);
            if (r0 + 8 < M)
                *(__half2*)(C + (size_t)(r0 + 8) * Ntot + col) =
                    __floats2half2_rn(acc[i][j][2], acc[i][j][3]);
        }
    }
}

// ---------------- SIMT SGEMM (layer0 only) — writes fp16 A ------------------
__global__ void __launch_bounds__(256)
sgemm0(const float* __restrict__ A, const float* __restrict__ B,
       __half* __restrict__ outA,
       int M, int N, int K, const float* __restrict__ bias)
{
    __shared__ float As[16][128];
    __shared__ float Bs[16][128];
    const int tid = threadIdx.x;
    const int m0 = blockIdx.y * 128;
    const int n0 = blockIdx.x * 128;
    const int tr = (tid >> 4) << 3;
    const int tc = (tid & 15) << 3;

    float acc[8][8];
    #pragma unroll
    for (int i = 0; i < 8; i++)
        #pragma unroll
        for (int j = 0; j < 8; j++) acc[i][j] = 0.f;

    for (int k0 = 0; k0 < K; k0 += 16) {
        #pragma unroll
        for (int it = 0; it < 2; it++) {
            int idx = tid + it * 256;
            int row = idx >> 2;
            int c4  = (idx & 3) << 2;
            float4 v = make_float4(0.f, 0.f, 0.f, 0.f);
            int gr = m0 + row;
            if (gr < M) v = *(const float4*)(A + (size_t)gr * K + k0 + c4);
            As[c4 + 0][row] = v.x;
            As[c4 + 1][row] = v.y;
            As[c4 + 2][row] = v.z;
            As[c4 + 3][row] = v.w;
        }
        #pragma unroll
        for (int it = 0; it < 2; it++) {
            int idx = tid + it * 256;
            int row = idx >> 5;
            int c4  = (idx & 31) << 2;
            float4 v = *(const float4*)(B + (size_t)(k0 + row) * N + n0 + c4);
            *(float4*)&Bs[row][c4] = v;
        }
        __syncthreads();
        #pragma unroll
        for (int k = 0; k < 16; k++) {
            float a[8], b[8];
            #pragma unroll
            for (int i = 0; i < 8; i++) a[i] = As[k][tr + i];
            #pragma unroll
            for (int j = 0; j < 8; j++) b[j] = Bs[k][tc + j];
            #pragma unroll
            for (int i = 0; i < 8; i++)
                #pragma unroll
                for (int j = 0; j < 8; j++)
                    acc[i][j] = fmaf(a[i], b[j], acc[i][j]);
        }
        __syncthreads();
    }

    #pragma unroll
    for (int i = 0; i < 8; i++) {
        int gr = m0 + tr + i;
        if (gr >= M) break;
        #pragma unroll
        for (int j = 0; j < 8; j += 2) {
            float v0 = lrelu(acc[i][j + 0] + bias[n0 + tc + j + 0]);
            float v1 = lrelu(acc[i][j + 1] + bias[n0 + tc + j + 1]);
            size_t o = (size_t)gr * N + n0 + tc + j;
            *(__half2*)(outA + o) = __floats2half2_rn(v0, v1);
        }
    }
}

// ---------------- gather with fused softmax (warp per dst,256-col chunk) ----
// fast path: deg <= 32 -> score loaded ONCE per lane, softmax in registers.
__global__ void __launch_bounds__(256)
gat_gather(const int* __restrict__ rowptr, const int* __restrict__ eids,
           const int* __restrict__ ei,
           const __half* __restrict__ hlin,
           const float* __restrict__ esrc, const float* __restrict__ edst,
           const float* __restrict__ bias,
           __half* __restrict__ outA,
           int H, int HC, int cshift)
{
    const int w = blockIdx.x * 8 + (threadIdx.x >> 5);
    const int lane = threadIdx.x & 31;
    const int d = w % NN;
    const int chunk = w / NN;
    const int c = chunk * 256 + lane * 8;
    const int h = (chunk * 256) >> cshift;      // warp-uniform head
    const int r0 = rowptr[d], r1 = rowptr[d + 1];
    const int deg = r1 - r0;
    const float ed = edst[d * H + h];

    float acc[8];
    #pragma unroll
    for (int q = 0; q < 8; q++) acc[q] = 0.f;

    if (deg <= 32) {
        // ---- single-batch fast path: score read once per lane ----
        int mys = 0;
        float sc = -FLT_MAX;
        if (lane < deg) {
            int eid = eids[r0 + lane];
            int s, dd; get_edge(ei, eid, s, dd);
            mys = s;
            sc = lrelu(esrc[s * H + h] + ed);
        }
        float mx = sc;
        #pragma unroll
        for (int o = 16; o > 0; o >>= 1)
            mx = fmaxf(mx, __shfl_xor_sync(0xFFFFFFFFu, mx, o));
        float ex = (lane < deg) ? __expf(sc - mx) : 0.f;
        float sm = ex;
        #pragma unroll
        for (int o = 16; o > 0; o >>= 1)
            sm += __shfl_xor_sync(0xFFFFFFFFu, sm, o);
        float mya = ex / (sm + 1e-16f);

        int j = 0;
        for (; j + 1 < deg; j += 2) {
            int s0 = __shfl_sync(0xFFFFFFFFu, mys, j);
            int s1 = __shfl_sync(0xFFFFFFFFu, mys, j + 1);
            float a0 = __shfl_sync(0xFFFFFFFFu, mya, j);
            float a1 = __shfl_sync(0xFFFFFFFFu, mya, j + 1);
            uint4 r0v = *(const uint4*)(hlin + (size_t)s0 * HC + c);
            uint4 r1v = *(const uint4*)(hlin + (size_t)s1 * HC + c);
            const __half2* h0 = (const __half2*)&r0v;
            const __half2* h1 = (const __half2*)&r1v;
            #pragma unroll
            for (int q = 0; q < 4; q++) {
                float2 f0 = __half22float2(h0[q]);
                float2 f1 = __half22float2(h1[q]);
                acc[q * 2 + 0] = fmaf(a0, f0.x, fmaf(a1, f1.x, acc[q * 2 + 0]));
                acc[q * 2 + 1] = fmaf(a0, f0.y, fmaf(a1, f1.y, acc[q * 2 + 1]));
            }
        }
        if (j < deg) {
            int s0 = __shfl_sync(0xFFFFFFFFu, mys, j);
            float a0 = __shfl_sync(0xFFFFFFFFu, mya, j);
            uint4 raw = *(const uint4*)(hlin + (size_t)s0 * HC + c);
            const __half2* hp = (const __half2*)&raw;
            #pragma unroll
            for (int q = 0; q < 4; q++) {
                float2 f = __half22float2(hp[q]);
                acc[q * 2 + 0] = fmaf(a0, f.x, acc[q * 2 + 0]);
                acc[q * 2 + 1] = fmaf(a0, f.y, acc[q * 2 + 1]);
            }
        }
    } else {
        // ---- general 3-pass fallback (rare) ----
        float mx = -FLT_MAX;
        for (int e0 = r0; e0 < r1; e0 += 32) {
            int e = e0 + lane;
            if (e < r1) {
                int eid = eids[e]; int s, dd; get_edge(ei, eid, s, dd);
                mx = fmaxf(mx, lrelu(esrc[s * H + h] + ed));
            }
        }
        #pragma unroll
        for (int o = 16; o > 0; o >>= 1)
            mx = fmaxf(mx, __shfl_xor_sync(0xFFFFFFFFu, mx, o));

        float sm = 0.f;
        for (int e0 = r0; e0 < r1; e0 += 32) {
            int e = e0 + lane;
            if (e < r1) {
                int eid = eids[e]; int s, dd; get_edge(ei, eid, s, dd);
                sm += __expf(lrelu(esrc[s * H + h] + ed) - mx);
            }
        }
        #pragma unroll
        for (int o = 16; o > 0; o >>= 1)
            sm += __shfl_xor_sync(0xFFFFFFFFu, sm, o);
        const float inv = 1.0f / (sm + 1e-16f);

        for (int e0 = r0; e0 < r1; e0 += 32) {
            int e = e0 + lane;
            int mys = 0; float mya = 0.f;
            if (e < r1) {
                int eid = eids[e]; int s, dd; get_edge(ei, eid, s, dd);
                mys = s;
                mya = __expf(lrelu(esrc[s * H + h] + ed) - mx) * inv;
            }
            int cnt = min(32, r1 - e0);
            for (int j = 0; j < cnt; j++) {
                int s0 = __shfl_sync(0xFFFFFFFFu, mys, j);
                float a0 = __shfl_sync(0xFFFFFFFFu, mya, j);
                uint4 raw = *(const uint4*)(hlin + (size_t)s0 * HC + c);
                const __half2* hp = (const __half2*)&raw;
                #pragma unroll
                for (int q = 0; q < 4; q++) {
                    float2 f = __half22float2(hp[q]);
                    acc[q * 2 + 0] = fmaf(a0, f.x, acc[q * 2 + 0]);
                    acc[q * 2 + 1] = fmaf(a0, f.y, acc[q * 2 + 1]);
                }
            }
        }
    }

    __half2 hx[4];
    #pragma unroll
    for (int q = 0; q < 4; q++) {
        float v0 = lrelu(acc[q * 2 + 0] + bias[c + q * 2 + 0]);
        float v1 = lrelu(acc[q * 2 + 1] + bias[c + q * 2 + 1]);
        hx[q] = __floats2half2_rn(v0, v1);
    }
    *(uint4*)(outA + (size_t)d * HC + c) = *(uint4*)hx;
}

// ---------------- pooling (sorted-batch run accumulation, fp16 input) -------
__global__ void pool2(const __half* __restrict__ h, const int* __restrict__ batch,
                      float* __restrict__ pool, float* __restrict__ cnt) {
    __shared__ int bid[128];
    int base = blockIdx.x * 128;
    int tid = threadIdx.x;
    for (int i = tid; i < 128; i += 256)
        bid[i] = (base + i < NN) ? batch[base + i] : -1;
    __syncthreads();
    int c = tid;
    float a0 = 0.f, a1 = 0.f;
    int rl = 0;
    int cur = bid[0];
    for (int i = 0; i < 128; i++) {
        int g = bid[i];
        if (g < 0) break;
        if (g != cur) {
            atomicAdd(&pool[cur * FEAT + c], a0);
            atomicAdd(&pool[cur * FEAT + c + 256], a1);
            if (tid == 0) atomicAdd(&cnt[cur], (float)rl);
            a0 = a1 = 0.f;
            rl = 0;
            cur = g;
        }
        const __half* row = h + (size_t)(base + i) * FEAT;
        a0 += __half2float(row[c]);
        a1 += __half2float(row[c + 256]);
        rl++;
    }
    if (cur >= 0) {
        atomicAdd(&pool[cur * FEAT + c], a0);
        atomicAdd(&pool[cur * FEAT + c + 256], a1);
        if (tid == 0) atomicAdd(&cnt[cur], (float)rl);
    }
}

__global__ void final_mlp(const float* __restrict__ pool, const float* __restrict__ cnt,
                          const float* __restrict__ Wf, const float* __restrict__ bf,
                          float* __restrict__ out)
{
    int g = blockIdx.x;
    int o = threadIdx.x;
    float inv = 1.0f / fmaxf(cnt[g], 1.0f);
    float acc = bf[o];
    const float* pg = pool + g * FEAT;
    #pragma unroll 8
    for (int k = 0; k < FEAT; k++)
        acc = fmaf(pg[k] * inv, Wf[k * FEAT + o], acc);
    out[g * FEAT + o] = lrelu(acc);
}

// ---------------- host orchestration ----------------------------------------
struct Ptrs {
    float *scores, *pool, *cnt;
    __half *hout, *hlin, *A, *B;
    int *rowptr, *deg, *cursor, *eids;
};

extern "C" void kernel_launch(void* const* d_in, const int* in_sizes, int n_in,
                              void* d_out, int out_size)
{
    const float* x     = (const float*)d_in[0];
    const int*   ei    = (const int*)  d_in[1];
    const int*   batch = (const int*)  d_in[2];
    const float* W0  = (const float*)d_in[3];
    const float* b0  = (const float*)d_in[4];
    const float* W1  = (const float*)d_in[5];
    const float* a1s = (const float*)d_in[6];
    const float* a1d = (const float*)d_in[7];
    const float* b1  = (const float*)d_in[8];
    const float* W2  = (const float*)d_in[9];
    const float* a2s = (const float*)d_in[10];
    const float* a2d = (const float*)d_in[11];
    const float* b2  = (const float*)d_in[12];
    const float* W3  = (const float*)d_in[13];
    const float* a3s = (const float*)d_in[14];
    const float* a3d = (const float*)d_in[15];
    const float* b3  = (const float*)d_in[16];
    const float* Wf  = (const float*)d_in[17];
    const float* bf  = (const float*)d_in[18];
    float* out = (float*)d_out;

    cudaFuncSetAttribute(wgemm, cudaFuncAttributeMaxDynamicSharedMemorySize, WG_SMEM);

    Ptrs P;
    cudaGetSymbolAddress((void**)&P.hout,   g_hout);
    cudaGetSymbolAddress((void**)&P.hlin,   g_hlin);
    cudaGetSymbolAddress((void**)&P.scores, g_scores);
    cudaGetSymbolAddress((void**)&P.pool,   g_pool);
    cudaGetSymbolAddress((void**)&P.cnt,    g_cnt);
    cudaGetSymbolAddress((void**)&P.A,      g_A);
    cudaGetSymbolAddress((void**)&P.B,      g_B);
    cudaGetSymbolAddress((void**)&P.rowptr, g_rowptr);
    cudaGetSymbolAddress((void**)&P.deg,    g_deg);
    cudaGetSymbolAddress((void**)&P.cursor, g_cursor);
    cudaGetSymbolAddress((void**)&P.eids,   g_eids);

    float* esrc = P.scores;
    float* edst = P.scores + NN * HEADS;

    const float* Ws[3]  = { W1, W2, W3 };
    const float* ass[3] = { a1s, a2s, a3s };
    const float* ads[3] = { a1d, a2d, a3d };
    const float* bs[3]  = { b1, b2, b3 };
    const int Kin[3]    = { EMB, HC1, HC1 };
    const int Hs[3]     = { HEADS, HEADS, 1 };
    const int Cs[3]     = { HID, HID, OUTC };
    const int cshifts[3]= { 8, 8, 9 };

    // 1: layer0 GEMM (writes fp16 A directly)
    {
        dim3 g0(EMB / 128, (NN + 127) / 128);
        sgemm0<<<g0, 256>>>(x, W0, P.A, NN, EMB, TILE_, b0);
    }
    // 2: weight convert for layer 1
    {
        dim3 tb(32, 8), tg(HC1 / 32, EMB / 32);
        tconv_t<<<tg, tb>>>(W1, P.B, EMB, HC1);
    }
    // 3: zero scores
    fillk<<<64, 256>>>(P.scores, 0.f, (size_t)2 * NN * HEADS);
    // 4: wgemm layer 1  <-- ncu capture slot
    {
        dim3 gg(HC1 / 128, (NN + 127) / 128);
        wgemm<<<gg, 256, WG_SMEM>>>(P.A, P.B, P.hlin, NN, HC1, EMB,
                                    a1s, a1d, esrc, edst, HEADS, HID);
    }
    // CSR build
    filli<<<(NN + 255) / 256, 256>>>(P.deg, 0, NN);
    count_deg<<<(ET + 255) / 256, 256>>>(ei, P.deg);
    scan_rowptr<<<1, 1024>>>(P.deg, P.rowptr, P.cursor);
    scatter_edges<<<(ET + 255) / 256, 256>>>(ei, P.cursor, P.eids);

    for (int L = 0; L < 3; L++) {
        int H = Hs[L], C = Cs[L], HC = H * C;
        if (L > 0) {
            dim3 tb(32, 8), tg(HC / 32, Kin[L] / 32);
            tconv_t<<<tg, tb>>>(Ws[L], P.B, Kin[L], HC);
            fillk<<<64, 256>>>(P.scores, 0.f, (size_t)2 * NN * HEADS);
            dim3 gg(HC / 128, (NN + 127) / 128);
            wgemm<<<gg, 256, WG_SMEM>>>(P.A, P.B, P.hlin, NN, HC, Kin[L],
                                        ass[L], ads[L], esrc, edst, H, C);
        }
        int nchunks = HC / 256;
        int nwarps = NN * nchunks;
        __half* dstA = (L == 2) ? P.hout : P.A;
        gat_gather<<<nwarps / 8, 256>>>(P.rowptr, P.eids, ei, P.hlin, esrc, edst,
                                        bs[L], dstA, H, HC, cshifts[L]);
    }

    // ---- global mean pool + final MLP ----
    fillk<<<32, 256>>>(P.pool, 0.f, (size_t)GG * FEAT);
    fillk<<<1, 32>>>(P.cnt, 0.f, (size_t)GG);
    pool2<<<(NN + 127) / 128, 256>>>(P.hout, batch, P.pool, P.cnt);
    final_mlp<<<GG, FEAT>>>(P.pool, P.cnt, Wf, bf, out);
}

// round 16
// speedup vs baseline: 1.0179x; 1.0149x over previous
#include <cuda_runtime.h>
#include <cuda_fp16.h>
#include <math.h>
#include <float.h>
#include <stdint.h>

// Problem constants
#define NN    20000
#define EE    100000
#define GG    16
#define ET    (EE + NN)      // edges incl. self loops = 120000
#define TILE_ 32
#define EMB   128
#define HID   256
#define OUTC  512
#define HEADS 8
#define FEAT  512
#define HC1   (HEADS * HID)  // 2048
#define SLOPE 0.2f

// ---------------- scratch (static device globals; no runtime alloc) --------
__device__ __half g_hout[(size_t)NN * FEAT];  // layer3 fp16 out (pool input)
__device__ __half g_hlin[(size_t)NN * HC1];   // h_lin (GEMM output, fp16)
__device__ float g_scores[2 * NN * HEADS];    // esrc | edst
__device__ float g_alpha[(size_t)ET * HEADS]; // indexed by CSR slot
__device__ float g_pool[GG * FEAT];
__device__ float g_cnt [GG];
// fp16 operands for tensor-core GEMMs
__device__ __half g_A [(size_t)NN * HC1];
__device__ __half g_B [(size_t)HC1 * HC1];    // weight^T fp16 [N,K]
// CSR (by destination): src node id per slot
__device__ int g_rowptr[NN + 1];
__device__ int g_deg[NN];
__device__ int g_cursor[NN];
__device__ int g_src[ET];

__device__ __forceinline__ float lrelu(float v) { return v > 0.f ? v : SLOPE * v; }

__device__ __forceinline__ void get_edge(const int* __restrict__ ei, int eid, int& s, int& d) {
    if (eid < EE) { s = ei[eid]; d = ei[EE + eid]; }
    else          { s = d = eid - EE; }
}

__device__ __forceinline__ uint32_t smem_u32(const void* p) {
    uint32_t a;
    asm("{ .reg .u64 t; cvta.to.shared.u64 t, %1; cvt.u32.u64 %0, t; }" : "=r"(a) : "l"(p));
    return a;
}

// ---------------- fills ------------------------------------------------------
__global__ void fillk(float* p, float v, size_t n) {
    size_t i = (size_t)blockIdx.x * blockDim.x + threadIdx.x;
    size_t stride = (size_t)gridDim.x * blockDim.x;
    for (; i < n; i += stride) p[i] = v;
}
__global__ void filli(int* p, int v, int n) {
    int i = blockIdx.x * blockDim.x + threadIdx.x;
    if (i < n) p[i] = v;
}

// ---------------- CSR build --------------------------------------------------
__global__ void count_deg(const int* __restrict__ ei, int* __restrict__ deg) {
    int eid = blockIdx.x * blockDim.x + threadIdx.x;
    if (eid >= ET) return;
    int s, d; get_edge(ei, eid, s, d);
    atomicAdd(&deg[d], 1);
}

__global__ void scan_rowptr(const int* __restrict__ deg, int* __restrict__ rowptr,
                            int* __restrict__ cursor) {
    __shared__ int buf[1024];
    __shared__ int carry;
    int tid = threadIdx.x;
    if (tid == 0) carry = 0;
    __syncthreads();
    for (int base = 0; base < NN; base += 1024) {
        int i = base + tid;
        int v = (i < NN) ? deg[i] : 0;
        buf[tid] = v;
        __syncthreads();
        for (int off = 1; off < 1024; off <<= 1) {
            int t = (tid >= off) ? buf[tid - off] : 0;
            __syncthreads();
            buf[tid] += t;
            __syncthreads();
        }
        if (i < NN) {
            int inc = carry + buf[tid];
            rowptr[i + 1] = inc;
            cursor[i] = inc - v;
        }
        __syncthreads();
        if (tid == 0) carry += buf[1023];
        __syncthreads();
    }
    if (tid == 0) rowptr[0] = 0;
}

// writes SOURCE node id into CSR slot (eid itself never needed downstream)
__global__ void scatter_edges(const int* __restrict__ ei, int* __restrict__ cur,
                              int* __restrict__ src) {
    int eid = blockIdx.x * blockDim.x + threadIdx.x;
    if (eid >= ET) return;
    int s, d; get_edge(ei, eid, s, d);
    int pos = atomicAdd(&cur[d], 1);
    src[pos] = s;
}

// =================== weight transpose to fp16 ================================
__global__ void tconv_t(const float* __restrict__ W, __half* __restrict__ o,
                        int K, int N) {
    __shared__ float t[32][33];
    int kb = blockIdx.y * 32, nb = blockIdx.x * 32;
    int tx = threadIdx.x, ty = threadIdx.y;
    #pragma unroll
    for (int i = ty; i < 32; i += 8)
        t[i][tx] = W[(size_t)(kb + i) * N + nb + tx];
    __syncthreads();
    #pragma unroll
    for (int i = ty; i < 32; i += 8)
        o[(size_t)(nb + i) * K + kb + tx] = __float2half_rn(t[tx][i]);
}

// =================== warp-MMA fp16 GEMM (K-chunk 64) =========================
// CTA tile 128x128, 8 warps (2x4), warp tile 64x32, K-chunk 64, 3-stage
// cp.async pipeline, 2 CTAs/SM. Smem rows stride 72 fp16 (144B, conflict-free).
#define WG_STRIDE  72
#define WG_T       (128 * WG_STRIDE * 2)   // 18432 B per 128x64 fp16 tile
#define WG_STAGE   (2 * WG_T)              // A, B = 36864
#define WG_STAGES  3
#define WG_SMEM    (WG_STAGES * WG_STAGE)  // 110592

__device__ __forceinline__ void lda4(uint32_t addr, uint32_t* r) {
    asm volatile("ldmatrix.sync.aligned.m8n8.x4.shared.b16 {%0,%1,%2,%3}, [%4];"
                 : "=r"(r[0]), "=r"(r[1]), "=r"(r[2]), "=r"(r[3]) : "r"(addr));
}

__device__ __forceinline__ void mma16816(float* d, const uint32_t* a, const uint32_t* b) {
    asm volatile("mma.sync.aligned.m16n8k16.row.col.f32.f16.f16.f32 "
                 "{%0,%1,%2,%3}, {%4,%5,%6,%7}, {%8,%9}, {%0,%1,%2,%3};"
                 : "+f"(d[0]), "+f"(d[1]), "+f"(d[2]), "+f"(d[3])
                 : "r"(a[0]), "r"(a[1]), "r"(a[2]), "r"(a[3]), "r"(b[0]), "r"(b[1]));
}

__global__ void __launch_bounds__(256, 2)
wgemm(const __half* __restrict__ A, const __half* __restrict__ B,
      __half* __restrict__ C, int M, int Ntot, int Ktot,
      const float* __restrict__ a_s, const float* __restrict__ a_d,
      float* __restrict__ esrc, float* __restrict__ edst, int H, int Cc)
{
    extern __shared__ char sm_[];
    const uint32_t smb = smem_u32(sm_);
    const int tid = threadIdx.x;
    const int lane = tid & 31, wid = tid >> 5;
    const int wm = wid & 1;          // 0..1 (64 rows each)
    const int wn = wid >> 1;         // 0..3 (32 cols each)
    const int m0 = blockIdx.y * 128;
    const int n0 = blockIdx.x * 128;
    const int NC = Ktot / 64;

    float acc[4][4][4];
    #pragma unroll
    for (int i = 0; i < 4; i++)
        #pragma unroll
        for (int j = 0; j < 4; j++)
            #pragma unroll
            for (int q = 0; q < 4; q++) acc[i][j][q] = 0.f;

    const int arow  = wm * 64 + (lane & 15);
    const int acolh = (lane >> 4) << 3;
    const int brow  = wn * 32 + (lane & 7) + ((lane >> 4) << 3);
    const int bcol  = lane & 8;

    auto load_stage = [&](int c, int st) {
        const int k0 = c * 64;
        const uint32_t sb = smb + st * WG_STAGE;
        #pragma unroll
        for (int i = 0; i < 4; i++) {
            int idx = tid + i * 256;
            int row = idx >> 3;
            int seg = idx & 7;
            int gr = m0 + row;
            int ok = gr < M;
            const __half* g = A + (size_t)(ok ? gr : 0) * Ktot + k0 + seg * 8;
            uint32_t dst = sb + row * (WG_STRIDE * 2) + seg * 16;
            int sz = ok ? 16 : 0;
            asm volatile("cp.async.cg.shared.global [%0], [%1], 16, %2;"
                         :: "r"(dst), "l"(g), "r"(sz));
        }
        #pragma unroll
        for (int i = 0; i < 4; i++) {
            int idx = tid + i * 256;
            int row = idx >> 3;
            int seg = idx & 7;
            const __half* g = B + (size_t)(n0 + row) * Ktot + k0 + seg * 8;
            uint32_t dst = sb + WG_T + row * (WG_STRIDE * 2) + seg * 16;
            asm volatile("cp.async.cg.shared.global [%0], [%1], 16, %2;"
                         :: "r"(dst), "l"(g), "r"(16));
        }
        asm volatile("cp.async.commit_group;" ::: "memory");
    };

    load_stage(0, 0);
    if (NC > 1) load_stage(1, 1);

    for (int c = 0; c < NC; c++) {
        if (c + 1 < NC) {
            asm volatile("cp.async.wait_group 1;" ::: "memory");
        } else {
            asm volatile("cp.async.wait_group 0;" ::: "memory");
        }
        __syncthreads();
        if (c + 2 < NC) load_stage(c + 2, (c + 2) % WG_STAGES);

        const uint32_t sb = smb + (c % WG_STAGES) * WG_STAGE;
        #pragma unroll
        for (int ks = 0; ks < 4; ks++) {
            uint32_t aH[4][4], bH[4][2];
            #pragma unroll
            for (int i = 0; i < 4; i++) {
                uint32_t off = (uint32_t)((arow + i * 16) * (WG_STRIDE * 2) +
                                          (ks * 16 + acolh) * 2);
                lda4(sb + off, aH[i]);
            }
            #pragma unroll
            for (int jp = 0; jp < 2; jp++) {
                uint32_t off = (uint32_t)((brow + jp * 16) * (WG_STRIDE * 2) +
                                          (ks * 16 + bcol) * 2);
                uint32_t t[4];
                lda4(sb + WG_T + off, t);
                bH[jp * 2][0] = t[0]; bH[jp * 2][1] = t[1];
                bH[jp * 2 + 1][0] = t[2]; bH[jp * 2 + 1][1] = t[3];
            }
            #pragma unroll
            for (int i = 0; i < 4; i++)
                #pragma unroll
                for (int j = 0; j < 4; j++)
                    mma16816(acc[i][j], aH[i], bH[j]);
        }
        __syncthreads();
    }

    // ---- fused attention-score epilogue ----
    {
        float* sAs = (float*)sm_;
        float* sAd = sAs + 128;
        if (tid < 128) { sAs[tid] = a_s[n0 + tid]; sAd[tid] = a_d[n0 + tid]; }
        __syncthreads();
        const int hh = n0 / Cc;
        #pragma unroll
        for (int i = 0; i < 4; i++) {
            float slo = 0.f, shi = 0.f, dlo = 0.f, dhi = 0.f;
            #pragma unroll
            for (int j = 0; j < 4; j++) {
                int cc = wn * 32 + j * 8 + 2 * (lane & 3);
                float A0 = sAs[cc], A1 = sAs[cc + 1];
                float D0 = sAd[cc], D1 = sAd[cc + 1];
                slo += acc[i][j][0] * A0 + acc[i][j][1] * A1;
                shi += acc[i][j][2] * A0 + acc[i][j][3] * A1;
                dlo += acc[i][j][0] * D0 + acc[i][j][1] * D1;
                dhi += acc[i][j][2] * D0 + acc[i][j][3] * D1;
            }
            #pragma unroll
            for (int o = 1; o < 4; o <<= 1) {
                slo += __shfl_xor_sync(0xFFFFFFFFu, slo, o);
                shi += __shfl_xor_sync(0xFFFFFFFFu, shi, o);
                dlo += __shfl_xor_sync(0xFFFFFFFFu, dlo, o);
                dhi += __shfl_xor_sync(0xFFFFFFFFu, dhi, o);
            }
            if ((lane & 3) == 0) {
                int r0 = m0 + wm * 64 + i * 16 + (lane >> 2);
                if (r0 < M) {
                    atomicAdd(&esrc[r0 * H + hh], slo);
                    atomicAdd(&edst[r0 * H + hh], dlo);
                }
                if (r0 + 8 < M) {
                    atomicAdd(&esrc[(r0 + 8) * H + hh], shi);
                    atomicAdd(&edst[(r0 + 8) * H + hh], dhi);
                }
            }
        }
    }

    // ---- C stores (fp16) ----
    #pragma unroll
    for (int i = 0; i < 4; i++) {
        int r0 = m0 + wm * 64 + i * 16 + (lane >> 2);
        #pragma unroll
        for (int j = 0; j < 4; j++) {
            int col = n0 + wn * 32 + j * 8 + 2 * (lane & 3);
            if (r0 < M)
                *(__half2*)(C + (size_t)r0 * Ntot + col) =
                    __floats2half2_rn(acc[i][j][0], acc[i][j][1]);
            if (r0 + 8 < M)
                *(__half2*)(C + (size_t)(r0 + 8) * Ntot + col) =
                    __floats2half2_rn(acc[i][j][2], acc[i][j][3]);
        }
    }
}

// ---------------- SIMT SGEMM (layer0 only) — writes fp16 A ------------------
__global__ void __launch_bounds__(256)
sgemm0(const float* __restrict__ A, const float* __restrict__ B,
       __half* __restrict__ outA,
       int M, int N, int K, const float* __restrict__ bias)
{
    __shared__ float As[16][128];
    __shared__ float Bs[16][128];
    const int tid = threadIdx.x;
    const int m0 = blockIdx.y * 128;
    const int n0 = blockIdx.x * 128;
    const int tr = (tid >> 4) << 3;
    const int tc = (tid & 15) << 3;

    float acc[8][8];
    #pragma unroll
    for (int i = 0; i < 8; i++)
        #pragma unroll
        for (int j = 0; j < 8; j++) acc[i][j] = 0.f;

    for (int k0 = 0; k0 < K; k0 += 16) {
        #pragma unroll
        for (int it = 0; it < 2; it++) {
            int idx = tid + it * 256;
            int row = idx >> 2;
            int c4  = (idx & 3) << 2;
            float4 v = make_float4(0.f, 0.f, 0.f, 0.f);
            int gr = m0 + row;
            if (gr < M) v = *(const float4*)(A + (size_t)gr * K + k0 + c4);
            As[c4 + 0][row] = v.x;
            As[c4 + 1][row] = v.y;
            As[c4 + 2][row] = v.z;
            As[c4 + 3][row] = v.w;
        }
        #pragma unroll
        for (int it = 0; it < 2; it++) {
            int idx = tid + it * 256;
            int row = idx >> 5;
            int c4  = (idx & 31) << 2;
            float4 v = *(const float4*)(B + (size_t)(k0 + row) * N + n0 + c4);
            *(float4*)&Bs[row][c4] = v;
        }
        __syncthreads();
        #pragma unroll
        for (int k = 0; k < 16; k++) {
            float a[8], b[8];
            #pragma unroll
            for (int i = 0; i < 8; i++) a[i] = As[k][tr + i];
            #pragma unroll
            for (int j = 0; j < 8; j++) b[j] = Bs[k][tc + j];
            #pragma unroll
            for (int i = 0; i < 8; i++)
                #pragma unroll
                for (int j = 0; j < 8; j++)
                    acc[i][j] = fmaf(a[i], b[j], acc[i][j]);
        }
        __syncthreads();
    }

    #pragma unroll
    for (int i = 0; i < 8; i++) {
        int gr = m0 + tr + i;
        if (gr >= M) break;
        #pragma unroll
        for (int j = 0; j < 8; j += 2) {
            float v0 = lrelu(acc[i][j + 0] + bias[n0 + tc + j + 0]);
            float v1 = lrelu(acc[i][j + 1] + bias[n0 + tc + j + 1]);
            size_t o = (size_t)gr * N + n0 + tc + j;
            *(__half2*)(outA + o) = __floats2half2_rn(v0, v1);
        }
    }
}

// ---------------- per-dst softmax alpha (CSR slot indexed, no atomics) ------
__global__ void gat_alpha(const int* __restrict__ rowptr, const int* __restrict__ src,
                          const float* __restrict__ esrc, const float* __restrict__ edst,
                          float* __restrict__ alpha, int H)
{
    int w = (blockIdx.x * blockDim.x + threadIdx.x) >> 5;
    int lane = threadIdx.x & 31;
    if (w >= NN) return;
    int d = w;
    int r0 = rowptr[d], r1 = rowptr[d + 1];
    float ed[8], mx[8], sm[8];
    if (H == 8) {
        float4 e0 = *(const float4*)(edst + d * 8);
        float4 e1 = *(const float4*)(edst + d * 8 + 4);
        ed[0] = e0.x; ed[1] = e0.y; ed[2] = e0.z; ed[3] = e0.w;
        ed[4] = e1.x; ed[5] = e1.y; ed[6] = e1.z; ed[7] = e1.w;
    } else {
        #pragma unroll
        for (int h = 0; h < 8; h++) ed[h] = (h < H) ? edst[d * H + h] : 0.f;
    }
    #pragma unroll
    for (int h = 0; h < 8; h++) { mx[h] = -FLT_MAX; sm[h] = 0.f; }

    for (int e = r0 + lane; e < r1; e += 32) {
        int s = src[e];
        if (H == 8) {
            float4 s0 = *(const float4*)(esrc + s * 8);
            float4 s1 = *(const float4*)(esrc + s * 8 + 4);
            float es[8] = { s0.x, s0.y, s0.z, s0.w, s1.x, s1.y, s1.z, s1.w };
            #pragma unroll
            for (int h = 0; h < 8; h++)
                mx[h] = fmaxf(mx[h], lrelu(es[h] + ed[h]));
        } else {
            mx[0] = fmaxf(mx[0], lrelu(esrc[s * H] + ed[0]));
        }
    }
    #pragma unroll
    for (int h = 0; h < 8; h++)
        #pragma unroll
        for (int o = 16; o > 0; o >>= 1)
            mx[h] = fmaxf(mx[h], __shfl_xor_sync(0xFFFFFFFFu, mx[h], o));

    for (int e = r0 + lane; e < r1; e += 32) {
        int s = src[e];
        if (H == 8) {
            float4 s0 = *(const float4*)(esrc + s * 8);
            float4 s1 = *(const float4*)(esrc + s * 8 + 4);
            float es[8] = { s0.x, s0.y, s0.z, s0.w, s1.x, s1.y, s1.z, s1.w };
            #pragma unroll
            for (int h = 0; h < 8; h++)
                sm[h] += __expf(lrelu(es[h] + ed[h]) - mx[h]);
        } else {
            sm[0] += __expf(lrelu(esrc[s * H] + ed[0]) - mx[0]);
        }
    }
    #pragma unroll
    for (int h = 0; h < 8; h++)
        #pragma unroll
        for (int o = 16; o > 0; o >>= 1)
            sm[h] += __shfl_xor_sync(0xFFFFFFFFu, sm[h], o);

    for (int e = r0 + lane; e < r1; e += 32) {
        int s = src[e];
        if (H == 8) {
            float4 s0 = *(const float4*)(esrc + s * 8);
            float4 s1 = *(const float4*)(esrc + s * 8 + 4);
            float es[8] = { s0.x, s0.y, s0.z, s0.w, s1.x, s1.y, s1.z, s1.w };
            float av[8];
            #pragma unroll
            for (int h = 0; h < 8; h++)
                av[h] = __expf(lrelu(es[h] + ed[h]) - mx[h]) / (sm[h] + 1e-16f);
            *(float4*)(alpha + (size_t)e * 8)     = make_float4(av[0], av[1], av[2], av[3]);
            *(float4*)(alpha + (size_t)e * 8 + 4) = make_float4(av[4], av[5], av[6], av[7]);
        } else {
            float v = __expf(lrelu(esrc[s * H] + ed[0]) - mx[0]);
            alpha[(size_t)e] = v / (sm[0] + 1e-16f);
        }
    }
}

// ---------------- gather: warp per (dst, 256-col chunk), fp16 hlin ----------
__global__ void __launch_bounds__(256)
gat_gather(const int* __restrict__ rowptr, const int* __restrict__ src,
           const __half* __restrict__ hlin, const float* __restrict__ alpha,
           const float* __restrict__ bias,
           __half* __restrict__ outA,
           int H, int HC, int cshift)
{
    const int w = blockIdx.x * 8 + (threadIdx.x >> 5);
    const int lane = threadIdx.x & 31;
    const int d = w % NN;
    const int chunk = w / NN;
    const int c = chunk * 256 + lane * 8;
    const int h = (chunk * 256) >> cshift;      // warp-uniform head
    const int r0 = rowptr[d], r1 = rowptr[d + 1];
    float acc[8];
    #pragma unroll
    for (int q = 0; q < 8; q++) acc[q] = 0.f;

    for (int e0 = r0; e0 < r1; e0 += 32) {
        int e = e0 + lane;
        int mys = 0; float mya = 0.f;
        if (e < r1) {
            mys = src[e];
            mya = alpha[(size_t)e * H + h];
        }
        int cnt = min(32, r1 - e0);
        int j = 0;
        for (; j + 1 < cnt; j += 2) {
            int s0 = __shfl_sync(0xFFFFFFFFu, mys, j);
            int s1 = __shfl_sync(0xFFFFFFFFu, mys, j + 1);
            float a0 = __shfl_sync(0xFFFFFFFFu, mya, j);
            float a1 = __shfl_sync(0xFFFFFFFFu, mya, j + 1);
            uint4 r0v = *(const uint4*)(hlin + (size_t)s0 * HC + c);
            uint4 r1v = *(const uint4*)(hlin + (size_t)s1 * HC + c);
            const __half2* h0 = (const __half2*)&r0v;
            const __half2* h1 = (const __half2*)&r1v;
            #pragma unroll
            for (int q = 0; q < 4; q++) {
                float2 f0 = __half22float2(h0[q]);
                float2 f1 = __half22float2(h1[q]);
                acc[q * 2 + 0] = fmaf(a0, f0.x, fmaf(a1, f1.x, acc[q * 2 + 0]));
                acc[q * 2 + 1] = fmaf(a0, f0.y, fmaf(a1, f1.y, acc[q * 2 + 1]));
            }
        }
        if (j < cnt) {
            int s0 = __shfl_sync(0xFFFFFFFFu, mys, j);
            float a0 = __shfl_sync(0xFFFFFFFFu, mya, j);
            uint4 raw = *(const uint4*)(hlin + (size_t)s0 * HC + c);
            const __half2* hp = (const __half2*)&raw;
            #pragma unroll
            for (int q = 0; q < 4; q++) {
                float2 f = __half22float2(hp[q]);
                acc[q * 2 + 0] = fmaf(a0, f.x, acc[q * 2 + 0]);
                acc[q * 2 + 1] = fmaf(a0, f.y, acc[q * 2 + 1]);
            }
        }
    }

    __half2 hx[4];
    #pragma unroll
    for (int q = 0; q < 4; q++) {
        float v0 = lrelu(acc[q * 2 + 0] + bias[c + q * 2 + 0]);
        float v1 = lrelu(acc[q * 2 + 1] + bias[c + q * 2 + 1]);
        hx[q] = __floats2half2_rn(v0, v1);
    }
    *(uint4*)(outA + (size_t)d * HC + c) = *(uint4*)hx;
}

// ---------------- pooling (sorted-batch run accumulation, fp16 input) -------
__global__ void pool2(const __half* __restrict__ h, const int* __restrict__ batch,
                      float* __restrict__ pool, float* __restrict__ cnt) {
    __shared__ int bid[128];
    int base = blockIdx.x * 128;
    int tid = threadIdx.x;
    for (int i = tid; i < 128; i += 256)
        bid[i] = (base + i < NN) ? batch[base + i] : -1;
    __syncthreads();
    int c = tid;
    float a0 = 0.f, a1 = 0.f;
    int rl = 0;
    int cur = bid[0];
    for (int i = 0; i < 128; i++) {
        int g = bid[i];
        if (g < 0) break;
        if (g != cur) {
            atomicAdd(&pool[cur * FEAT + c], a0);
            atomicAdd(&pool[cur * FEAT + c + 256], a1);
            if (tid == 0) atomicAdd(&cnt[cur], (float)rl);
            a0 = a1 = 0.f;
            rl = 0;
            cur = g;
        }
        const __half* row = h + (size_t)(base + i) * FEAT;
        a0 += __half2float(row[c]);
        a1 += __half2float(row[c + 256]);
        rl++;
    }
    if (cur >= 0) {
        atomicAdd(&pool[cur * FEAT + c], a0);
        atomicAdd(&pool[cur * FEAT + c + 256], a1);
        if (tid == 0) atomicAdd(&cnt[cur], (float)rl);
    }
}

__global__ void final_mlp(const float* __restrict__ pool, const float* __restrict__ cnt,
                          const float* __restrict__ Wf, const float* __restrict__ bf,
                          float* __restrict__ out)
{
    int g = blockIdx.x;
    int o = threadIdx.x;
    float inv = 1.0f / fmaxf(cnt[g], 1.0f);
    float acc = bf[o];
    const float* pg = pool + g * FEAT;
    #pragma unroll 8
    for (int k = 0; k < FEAT; k++)
        acc = fmaf(pg[k] * inv, Wf[k * FEAT + o], acc);
    out[g * FEAT + o] = lrelu(acc);
}

// ---------------- host orchestration ----------------------------------------
struct Ptrs {
    float *scores, *alpha, *pool, *cnt;
    __half *hout, *hlin, *A, *B;
    int *rowptr, *deg, *cursor, *src;
};

extern "C" void kernel_launch(void* const* d_in, const int* in_sizes, int n_in,
                              void* d_out, int out_size)
{
    const float* x     = (const float*)d_in[0];
    const int*   ei    = (const int*)  d_in[1];
    const int*   batch = (const int*)  d_in[2];
    const float* W0  = (const float*)d_in[3];
    const float* b0  = (const float*)d_in[4];
    const float* W1  = (const float*)d_in[5];
    const float* a1s = (const float*)d_in[6];
    const float* a1d = (const float*)d_in[7];
    const float* b1  = (const float*)d_in[8];
    const float* W2  = (const float*)d_in[9];
    const float* a2s = (const float*)d_in[10];
    const float* a2d = (const float*)d_in[11];
    const float* b2  = (const float*)d_in[12];
    const float* W3  = (const float*)d_in[13];
    const float* a3s = (const float*)d_in[14];
    const float* a3d = (const float*)d_in[15];
    const float* b3  = (const float*)d_in[16];
    const float* Wf  = (const float*)d_in[17];
    const float* bf  = (const float*)d_in[18];
    float* out = (float*)d_out;

    cudaFuncSetAttribute(wgemm, cudaFuncAttributeMaxDynamicSharedMemorySize, WG_SMEM);

    Ptrs P;
    cudaGetSymbolAddress((void**)&P.hout,   g_hout);
    cudaGetSymbolAddress((void**)&P.hlin,   g_hlin);
    cudaGetSymbolAddress((void**)&P.scores, g_scores);
    cudaGetSymbolAddress((void**)&P.alpha,  g_alpha);
    cudaGetSymbolAddress((void**)&P.pool,   g_pool);
    cudaGetSymbolAddress((void**)&P.cnt,    g_cnt);
    cudaGetSymbolAddress((void**)&P.A,      g_A);
    cudaGetSymbolAddress((void**)&P.B,      g_B);
    cudaGetSymbolAddress((void**)&P.rowptr, g_rowptr);
    cudaGetSymbolAddress((void**)&P.deg,    g_deg);
    cudaGetSymbolAddress((void**)&P.cursor, g_cursor);
    cudaGetSymbolAddress((void**)&P.src,    g_src);

    float* esrc = P.scores;
    float* edst = P.scores + NN * HEADS;

    const float* Ws[3]  = { W1, W2, W3 };
    const float* ass[3] = { a1s, a2s, a3s };
    const float* ads[3] = { a1d, a2d, a3d };
    const float* bs[3]  = { b1, b2, b3 };
    const int Kin[3]    = { EMB, HC1, HC1 };
    const int Hs[3]     = { HEADS, HEADS, 1 };
    const int Cs[3]     = { HID, HID, OUTC };
    const int cshifts[3]= { 8, 8, 9 };

    // 1: layer0 GEMM (writes fp16 A directly)
    {
        dim3 g0(EMB / 128, (NN + 127) / 128);
        sgemm0<<<g0, 256>>>(x, W0, P.A, NN, EMB, TILE_, b0);
    }
    // 2: weight convert for layer 1
    {
        dim3 tb(32, 8), tg(HC1 / 32, EMB / 32);
        tconv_t<<<tg, tb>>>(W1, P.B, EMB, HC1);
    }
    // 3: zero scores
    fillk<<<64, 256>>>(P.scores, 0.f, (size_t)2 * NN * HEADS);
    // 4: wgemm layer 1  <-- ncu capture slot
    {
        dim3 gg(HC1 / 128, (NN + 127) / 128);
        wgemm<<<gg, 256, WG_SMEM>>>(P.A, P.B, P.hlin, NN, HC1, EMB,
                                    a1s, a1d, esrc, edst, HEADS, HID);
    }
    // CSR build
    filli<<<(NN + 255) / 256, 256>>>(P.deg, 0, NN);
    count_deg<<<(ET + 255) / 256, 256>>>(ei, P.deg);
    scan_rowptr<<<1, 1024>>>(P.deg, P.rowptr, P.cursor);
    scatter_edges<<<(ET + 255) / 256, 256>>>(ei, P.cursor, P.src);

    for (int L = 0; L < 3; L++) {
        int H = Hs[L], C = Cs[L], HC = H * C;
        if (L > 0) {
            dim3 tb(32, 8), tg(HC / 32, Kin[L] / 32);
            tconv_t<<<tg, tb>>>(Ws[L], P.B, Kin[L], HC);
            fillk<<<64, 256>>>(P.scores, 0.f, (size_t)2 * NN * HEADS);
            dim3 gg(HC / 128, (NN + 127) / 128);
            wgemm<<<gg, 256, WG_SMEM>>>(P.A, P.B, P.hlin, NN, HC, Kin[L],
                                        ass[L], ads[L], esrc, edst, H, C);
        }
        gat_alpha<<<(NN * 32 + 255) / 256, 256>>>(P.rowptr, P.src, esrc, edst,
                                                  P.alpha, H);
        int nchunks = HC / 256;
        int nwarps = NN * nchunks;
        __half* dstA = (L == 2) ? P.hout : P.A;
        gat_gather<<<nwarps / 8, 256>>>(P.rowptr, P.src, P.hlin, P.alpha,
                                        bs[L], dstA, H, HC, cshifts[L]);
    }

    // ---- global mean pool + final MLP ----
    fillk<<<32, 256>>>(P.pool, 0.f, (size_t)GG * FEAT);
    fillk<<<1, 32>>>(P.cnt, 0.f, (size_t)GG);
    pool2<<<(NN + 127) / 128, 256>>>(P.hout, batch, P.pool, P.cnt);
    final_mlp<<<GG, FEAT>>>(P.pool, P.cnt, Wf, bf, out);
}

// round 17
// speedup vs baseline: 1.0191x; 1.0012x over previous
#include <cuda_runtime.h>
#include <cuda_fp16.h>
#include <math.h>
#include <float.h>
#include <stdint.h>

// Problem constants
#define NN    20000
#define EE    100000
#define GG    16
#define ET    (EE + NN)      // edges incl. self loops = 120000
#define TILE_ 32
#define EMB   128
#define HID   256
#define OUTC  512
#define HEADS 8
#define FEAT  512
#define HC1   (HEADS * HID)  // 2048
#define SLOPE 0.2f

// ---------------- scratch (static device globals; no runtime alloc) --------
__device__ __half g_hout[(size_t)NN * FEAT];  // layer3 fp16 out (pool input)
__device__ __half g_hlin[(size_t)NN * HC1];   // h_lin (GEMM output, fp16)
__device__ float g_scores[2 * NN * HEADS];    // esrc | edst
__device__ float g_alpha[(size_t)ET * HEADS]; // indexed by CSR slot
__device__ float g_pool[GG * FEAT];
__device__ float g_cnt [GG];
// fp16 operands for tensor-core GEMMs
__device__ __half g_A [(size_t)NN * HC1];
__device__ __half g_B [(size_t)HC1 * HC1];    // weight^T fp16 [N,K]
// CSR (by destination): src node id per slot
__device__ int g_rowptr[NN + 1];
__device__ int g_deg[NN];
__device__ int g_cursor[NN];
__device__ int g_src[ET];

__device__ __forceinline__ float lrelu(float v) { return v > 0.f ? v : SLOPE * v; }

__device__ __forceinline__ void get_edge(const int* __restrict__ ei, int eid, int& s, int& d) {
    if (eid < EE) { s = ei[eid]; d = ei[EE + eid]; }
    else          { s = d = eid - EE; }
}

__device__ __forceinline__ uint32_t smem_u32(const void* p) {
    uint32_t a;
    asm("{ .reg .u64 t; cvta.to.shared.u64 t, %1; cvt.u32.u64 %0, t; }" : "=r"(a) : "l"(p));
    return a;
}

// ---------------- fills ------------------------------------------------------
__global__ void fillk(float* p, float v, size_t n) {
    size_t i = (size_t)blockIdx.x * blockDim.x + threadIdx.x;
    size_t stride = (size_t)gridDim.x * blockDim.x;
    for (; i < n; i += stride) p[i] = v;
}
__global__ void filli(int* p, int v, int n) {
    int i = blockIdx.x * blockDim.x + threadIdx.x;
    if (i < n) p[i] = v;
}

// ---------------- CSR build --------------------------------------------------
__global__ void count_deg(const int* __restrict__ ei, int* __restrict__ deg) {
    int eid = blockIdx.x * blockDim.x + threadIdx.x;
    if (eid >= ET) return;
    int s, d; get_edge(ei, eid, s, d);
    atomicAdd(&deg[d], 1);
}

__global__ void scan_rowptr(const int* __restrict__ deg, int* __restrict__ rowptr,
                            int* __restrict__ cursor) {
    __shared__ int buf[1024];
    __shared__ int carry;
    int tid = threadIdx.x;
    if (tid == 0) carry = 0;
    __syncthreads();
    for (int base = 0; base < NN; base += 1024) {
        int i = base + tid;
        int v = (i < NN) ? deg[i] : 0;
        buf[tid] = v;
        __syncthreads();
        for (int off = 1; off < 1024; off <<= 1) {
            int t = (tid >= off) ? buf[tid - off] : 0;
            __syncthreads();
            buf[tid] += t;
            __syncthreads();
        }
        if (i < NN) {
            int inc = carry + buf[tid];
            rowptr[i + 1] = inc;
            cursor[i] = inc - v;
        }
        __syncthreads();
        if (tid == 0) carry += buf[1023];
        __syncthreads();
    }
    if (tid == 0) rowptr[0] = 0;
}

// writes SOURCE node id into CSR slot
__global__ void scatter_edges(const int* __restrict__ ei, int* __restrict__ cur,
                              int* __restrict__ src) {
    int eid = blockIdx.x * blockDim.x + threadIdx.x;
    if (eid >= ET) return;
    int s, d; get_edge(ei, eid, s, d);
    int pos = atomicAdd(&cur[d], 1);
    src[pos] = s;
}

// =================== weight transpose to fp16 ================================
__global__ void tconv_t(const float* __restrict__ W, __half* __restrict__ o,
                        int K, int N) {
    __shared__ float t[32][33];
    int kb = blockIdx.y * 32, nb = blockIdx.x * 32;
    int tx = threadIdx.x, ty = threadIdx.y;
    #pragma unroll
    for (int i = ty; i < 32; i += 8)
        t[i][tx] = W[(size_t)(kb + i) * N + nb + tx];
    __syncthreads();
    #pragma unroll
    for (int i = ty; i < 32; i += 8)
        o[(size_t)(nb + i) * K + kb + tx] = __float2half_rn(t[tx][i]);
}

// =================== warp-MMA fp16 GEMM (K-chunk 64) =========================
#define WG_STRIDE  72
#define WG_T       (128 * WG_STRIDE * 2)   // 18432 B per 128x64 fp16 tile
#define WG_STAGE   (2 * WG_T)              // A, B = 36864
#define WG_STAGES  3
#define WG_SMEM    (WG_STAGES * WG_STAGE)  // 110592

__device__ __forceinline__ void lda4(uint32_t addr, uint32_t* r) {
    asm volatile("ldmatrix.sync.aligned.m8n8.x4.shared.b16 {%0,%1,%2,%3}, [%4];"
                 : "=r"(r[0]), "=r"(r[1]), "=r"(r[2]), "=r"(r[3]) : "r"(addr));
}

__device__ __forceinline__ void mma16816(float* d, const uint32_t* a, const uint32_t* b) {
    asm volatile("mma.sync.aligned.m16n8k16.row.col.f32.f16.f16.f32 "
                 "{%0,%1,%2,%3}, {%4,%5,%6,%7}, {%8,%9}, {%0,%1,%2,%3};"
                 : "+f"(d[0]), "+f"(d[1]), "+f"(d[2]), "+f"(d[3])
                 : "r"(a[0]), "r"(a[1]), "r"(a[2]), "r"(a[3]), "r"(b[0]), "r"(b[1]));
}

__global__ void __launch_bounds__(256, 2)
wgemm(const __half* __restrict__ A, const __half* __restrict__ B,
      __half* __restrict__ C, int M, int Ntot, int Ktot,
      const float* __restrict__ a_s, const float* __restrict__ a_d,
      float* __restrict__ esrc, float* __restrict__ edst, int H, int Cc)
{
    extern __shared__ char sm_[];
    const uint32_t smb = smem_u32(sm_);
    const int tid = threadIdx.x;
    const int lane = tid & 31, wid = tid >> 5;
    const int wm = wid & 1;
    const int wn = wid >> 1;
    const int m0 = blockIdx.y * 128;
    const int n0 = blockIdx.x * 128;
    const int NC = Ktot / 64;

    float acc[4][4][4];
    #pragma unroll
    for (int i = 0; i < 4; i++)
        #pragma unroll
        for (int j = 0; j < 4; j++)
            #pragma unroll
            for (int q = 0; q < 4; q++) acc[i][j][q] = 0.f;

    const int arow  = wm * 64 + (lane & 15);
    const int acolh = (lane >> 4) << 3;
    const int brow  = wn * 32 + (lane & 7) + ((lane >> 4) << 3);
    const int bcol  = lane & 8;

    auto load_stage = [&](int c, int st) {
        const int k0 = c * 64;
        const uint32_t sb = smb + st * WG_STAGE;
        #pragma unroll
        for (int i = 0; i < 4; i++) {
            int idx = tid + i * 256;
            int row = idx >> 3;
            int seg = idx & 7;
            int gr = m0 + row;
            int ok = gr < M;
            const __half* g = A + (size_t)(ok ? gr : 0) * Ktot + k0 + seg * 8;
            uint32_t dst = sb + row * (WG_STRIDE * 2) + seg * 16;
            int sz = ok ? 16 : 0;
            asm volatile("cp.async.cg.shared.global [%0], [%1], 16, %2;"
                         :: "r"(dst), "l"(g), "r"(sz));
        }
        #pragma unroll
        for (int i = 0; i < 4; i++) {
            int idx = tid + i * 256;
            int row = idx >> 3;
            int seg = idx & 7;
            const __half* g = B + (size_t)(n0 + row) * Ktot + k0 + seg * 8;
            uint32_t dst = sb + WG_T + row * (WG_STRIDE * 2) + seg * 16;
            asm volatile("cp.async.cg.shared.global [%0], [%1], 16, %2;"
                         :: "r"(dst), "l"(g), "r"(16));
        }
        asm volatile("cp.async.commit_group;" ::: "memory");
    };

    load_stage(0, 0);
    if (NC > 1) load_stage(1, 1);

    for (int c = 0; c < NC; c++) {
        if (c + 1 < NC) {
            asm volatile("cp.async.wait_group 1;" ::: "memory");
        } else {
            asm volatile("cp.async.wait_group 0;" ::: "memory");
        }
        __syncthreads();
        if (c + 2 < NC) load_stage(c + 2, (c + 2) % WG_STAGES);

        const uint32_t sb = smb + (c % WG_STAGES) * WG_STAGE;
        #pragma unroll
        for (int ks = 0; ks < 4; ks++) {
            uint32_t aH[4][4], bH[4][2];
            #pragma unroll
            for (int i = 0; i < 4; i++) {
                uint32_t off = (uint32_t)((arow + i * 16) * (WG_STRIDE * 2) +
                                          (ks * 16 + acolh) * 2);
                lda4(sb + off, aH[i]);
            }
            #pragma unroll
            for (int jp = 0; jp < 2; jp++) {
                uint32_t off = (uint32_t)((brow + jp * 16) * (WG_STRIDE * 2) +
                                          (ks * 16 + bcol) * 2);
                uint32_t t[4];
                lda4(sb + WG_T + off, t);
                bH[jp * 2][0] = t[0]; bH[jp * 2][1] = t[1];
                bH[jp * 2 + 1][0] = t[2]; bH[jp * 2 + 1][1] = t[3];
            }
            #pragma unroll
            for (int i = 0; i < 4; i++)
                #pragma unroll
                for (int j = 0; j < 4; j++)
                    mma16816(acc[i][j], aH[i], bH[j]);
        }
        __syncthreads();
    }

    // ---- fused attention-score epilogue ----
    {
        float* sAs = (float*)sm_;
        float* sAd = sAs + 128;
        if (tid < 128) { sAs[tid] = a_s[n0 + tid]; sAd[tid] = a_d[n0 + tid]; }
        __syncthreads();
        const int hh = n0 / Cc;
        #pragma unroll
        for (int i = 0; i < 4; i++) {
            float slo = 0.f, shi = 0.f, dlo = 0.f, dhi = 0.f;
            #pragma unroll
            for (int j = 0; j < 4; j++) {
                int cc = wn * 32 + j * 8 + 2 * (lane & 3);
                float A0 = sAs[cc], A1 = sAs[cc + 1];
                float D0 = sAd[cc], D1 = sAd[cc + 1];
                slo += acc[i][j][0] * A0 + acc[i][j][1] * A1;
                shi += acc[i][j][2] * A0 + acc[i][j][3] * A1;
                dlo += acc[i][j][0] * D0 + acc[i][j][1] * D1;
                dhi += acc[i][j][2] * D0 + acc[i][j][3] * D1;
            }
            #pragma unroll
            for (int o = 1; o < 4; o <<= 1) {
                slo += __shfl_xor_sync(0xFFFFFFFFu, slo, o);
                shi += __shfl_xor_sync(0xFFFFFFFFu, shi, o);
                dlo += __shfl_xor_sync(0xFFFFFFFFu, dlo, o);
                dhi += __shfl_xor_sync(0xFFFFFFFFu, dhi, o);
            }
            if ((lane & 3) == 0) {
                int r0 = m0 + wm * 64 + i * 16 + (lane >> 2);
                if (r0 < M) {
                    atomicAdd(&esrc[r0 * H + hh], slo);
                    atomicAdd(&edst[r0 * H + hh], dlo);
                }
                if (r0 + 8 < M) {
                    atomicAdd(&esrc[(r0 + 8) * H + hh], shi);
                    atomicAdd(&edst[(r0 + 8) * H + hh], dhi);
                }
            }
        }
    }

    // ---- C stores (fp16) ----
    #pragma unroll
    for (int i = 0; i < 4; i++) {
        int r0 = m0 + wm * 64 + i * 16 + (lane >> 2);
        #pragma unroll
        for (int j = 0; j < 4; j++) {
            int col = n0 + wn * 32 + j * 8 + 2 * (lane & 3);
            if (r0 < M)
                *(__half2*)(C + (size_t)r0 * Ntot + col) =
                    __floats2half2_rn(acc[i][j][0], acc[i][j][1]);
            if (r0 + 8 < M)
                *(__half2*)(C + (size_t)(r0 + 8) * Ntot + col) =
                    __floats2half2_rn(acc[i][j][2], acc[i][j][3]);
        }
    }
}

// ---------------- SIMT SGEMM (layer0 only) — writes fp16 A ------------------
__global__ void __launch_bounds__(256)
sgemm0(const float* __restrict__ A, const float* __restrict__ B,
       __half* __restrict__ outA,
       int M, int N, int K, const float* __restrict__ bias)
{
    __shared__ float As[16][128];
    __shared__ float Bs[16][128];
    const int tid = threadIdx.x;
    const int m0 = blockIdx.y * 128;
    const int n0 = blockIdx.x * 128;
    const int tr = (tid >> 4) << 3;
    const int tc = (tid & 15) << 3;

    float acc[8][8];
    #pragma unroll
    for (int i = 0; i < 8; i++)
        #pragma unroll
        for (int j = 0; j < 8; j++) acc[i][j] = 0.f;

    for (int k0 = 0; k0 < K; k0 += 16) {
        #pragma unroll
        for (int it = 0; it < 2; it++) {
            int idx = tid + it * 256;
            int row = idx >> 2;
            int c4  = (idx & 3) << 2;
            float4 v = make_float4(0.f, 0.f, 0.f, 0.f);
            int gr = m0 + row;
            if (gr < M) v = *(const float4*)(A + (size_t)gr * K + k0 + c4);
            As[c4 + 0][row] = v.x;
            As[c4 + 1][row] = v.y;
            As[c4 + 2][row] = v.z;
            As[c4 + 3][row] = v.w;
        }
        #pragma unroll
        for (int it = 0; it < 2; it++) {
            int idx = tid + it * 256;
            int row = idx >> 5;
            int c4  = (idx & 31) << 2;
            float4 v = *(const float4*)(B + (size_t)(k0 + row) * N + n0 + c4);
            *(float4*)&Bs[row][c4] = v;
        }
        __syncthreads();
        #pragma unroll
        for (int k = 0; k < 16; k++) {
            float a[8], b[8];
            #pragma unroll
            for (int i = 0; i < 8; i++) a[i] = As[k][tr + i];
            #pragma unroll
            for (int j = 0; j < 8; j++) b[j] = Bs[k][tc + j];
            #pragma unroll
            for (int i = 0; i < 8; i++)
                #pragma unroll
                for (int j = 0; j < 8; j++)
                    acc[i][j] = fmaf(a[i], b[j], acc[i][j]);
        }
        __syncthreads();
    }

    #pragma unroll
    for (int i = 0; i < 8; i++) {
        int gr = m0 + tr + i;
        if (gr >= M) break;
        #pragma unroll
        for (int j = 0; j < 8; j += 2) {
            float v0 = lrelu(acc[i][j + 0] + bias[n0 + tc + j + 0]);
            float v1 = lrelu(acc[i][j + 1] + bias[n0 + tc + j + 1]);
            size_t o = (size_t)gr * N + n0 + tc + j;
            *(__half2*)(outA + o) = __floats2half2_rn(v0, v1);
        }
    }
}

// ---------------- per-dst softmax alpha (single-pass fast path) -------------
__global__ void gat_alpha(const int* __restrict__ rowptr, const int* __restrict__ src,
                          const float* __restrict__ esrc, const float* __restrict__ edst,
                          float* __restrict__ alpha, int H)
{
    int w = (blockIdx.x * blockDim.x + threadIdx.x) >> 5;
    int lane = threadIdx.x & 31;
    if (w >= NN) return;
    int d = w;
    int r0 = rowptr[d], r1 = rowptr[d + 1];
    int deg = r1 - r0;

    float ed[8];
    if (H == 8) {
        float4 e0 = *(const float4*)(edst + d * 8);
        float4 e1 = *(const float4*)(edst + d * 8 + 4);
        ed[0] = e0.x; ed[1] = e0.y; ed[2] = e0.z; ed[3] = e0.w;
        ed[4] = e1.x; ed[5] = e1.y; ed[6] = e1.z; ed[7] = e1.w;
    } else {
        #pragma unroll
        for (int h = 0; h < 8; h++) ed[h] = (h < H) ? edst[d * H + h] : 0.f;
    }

    if (deg <= 32) {
        // ---- single-pass: each lane owns one edge, score loaded once ----
        int e = r0 + lane;
        int active = lane < deg;
        float sc[8];
        #pragma unroll
        for (int h = 0; h < 8; h++) sc[h] = -FLT_MAX;
        if (active) {
            int s = src[e];
            if (H == 8) {
                float4 s0 = *(const float4*)(esrc + s * 8);
                float4 s1 = *(const float4*)(esrc + s * 8 + 4);
                float es[8] = { s0.x, s0.y, s0.z, s0.w, s1.x, s1.y, s1.z, s1.w };
                #pragma unroll
                for (int h = 0; h < 8; h++) sc[h] = lrelu(es[h] + ed[h]);
            } else {
                sc[0] = lrelu(esrc[s * H] + ed[0]);
            }
        }
        float mx[8], ex[8], sm[8];
        #pragma unroll
        for (int h = 0; h < 8; h++) {
            mx[h] = sc[h];
            #pragma unroll
            for (int o = 16; o > 0; o >>= 1)
                mx[h] = fmaxf(mx[h], __shfl_xor_sync(0xFFFFFFFFu, mx[h], o));
            ex[h] = active ? __expf(sc[h] - mx[h]) : 0.f;
            sm[h] = ex[h];
            #pragma unroll
            for (int o = 16; o > 0; o >>= 1)
                sm[h] += __shfl_xor_sync(0xFFFFFFFFu, sm[h], o);
        }
        if (active) {
            if (H == 8) {
                float av[8];
                #pragma unroll
                for (int h = 0; h < 8; h++)
                    av[h] = ex[h] / (sm[h] + 1e-16f);
                *(float4*)(alpha + (size_t)e * 8)     = make_float4(av[0], av[1], av[2], av[3]);
                *(float4*)(alpha + (size_t)e * 8 + 4) = make_float4(av[4], av[5], av[6], av[7]);
            } else {
                alpha[(size_t)e] = ex[0] / (sm[0] + 1e-16f);
            }
        }
        return;
    }

    // ---- general 3-pass fallback (deg > 32, rare) ----
    float mx[8], sm[8];
    #pragma unroll
    for (int h = 0; h < 8; h++) { mx[h] = -FLT_MAX; sm[h] = 0.f; }

    for (int e = r0 + lane; e < r1; e += 32) {
        int s = src[e];
        if (H == 8) {
            float4 s0 = *(const float4*)(esrc + s * 8);
            float4 s1 = *(const float4*)(esrc + s * 8 + 4);
            float es[8] = { s0.x, s0.y, s0.z, s0.w, s1.x, s1.y, s1.z, s1.w };
            #pragma unroll
            for (int h = 0; h < 8; h++)
                mx[h] = fmaxf(mx[h], lrelu(es[h] + ed[h]));
        } else {
            mx[0] = fmaxf(mx[0], lrelu(esrc[s * H] + ed[0]));
        }
    }
    #pragma unroll
    for (int h = 0; h < 8; h++)
        #pragma unroll
        for (int o = 16; o > 0; o >>= 1)
            mx[h] = fmaxf(mx[h], __shfl_xor_sync(0xFFFFFFFFu, mx[h], o));

    for (int e = r0 + lane; e < r1; e += 32) {
        int s = src[e];
        if (H == 8) {
            float4 s0 = *(const float4*)(esrc + s * 8);
            float4 s1 = *(const float4*)(esrc + s * 8 + 4);
            float es[8] = { s0.x, s0.y, s0.z, s0.w, s1.x, s1.y, s1.z, s1.w };
            #pragma unroll
            for (int h = 0; h < 8; h++)
                sm[h] += __expf(lrelu(es[h] + ed[h]) - mx[h]);
        } else {
            sm[0] += __expf(lrelu(esrc[s * H] + ed[0]) - mx[0]);
        }
    }
    #pragma unroll
    for (int h = 0; h < 8; h++)
        #pragma unroll
        for (int o = 16; o > 0; o >>= 1)
            sm[h] += __shfl_xor_sync(0xFFFFFFFFu, sm[h], o);

    for (int e = r0 + lane; e < r1; e += 32) {
        int s = src[e];
        if (H == 8) {
            float4 s0 = *(const float4*)(esrc + s * 8);
            float4 s1 = *(const float4*)(esrc + s * 8 + 4);
            float es[8] = { s0.x, s0.y, s0.z, s0.w, s1.x, s1.y, s1.z, s1.w };
            float av[8];
            #pragma unroll
            for (int h = 0; h < 8; h++)
                av[h] = __expf(lrelu(es[h] + ed[h]) - mx[h]) / (sm[h] + 1e-16f);
            *(float4*)(alpha + (size_t)e * 8)     = make_float4(av[0], av[1], av[2], av[3]);
            *(float4*)(alpha + (size_t)e * 8 + 4) = make_float4(av[4], av[5], av[6], av[7]);
        } else {
            float v = __expf(lrelu(esrc[s * H] + ed[0]) - mx[0]);
            alpha[(size_t)e] = v / (sm[0] + 1e-16f);
        }
    }
}

// ---------------- gather: warp per (dst, 256-col chunk), unroll x4 ----------
__global__ void __launch_bounds__(256)
gat_gather(const int* __restrict__ rowptr, const int* __restrict__ src,
           const __half* __restrict__ hlin, const float* __restrict__ alpha,
           const float* __restrict__ bias,
           __half* __restrict__ outA,
           int H, int HC, int cshift)
{
    const int w = blockIdx.x * 8 + (threadIdx.x >> 5);
    const int lane = threadIdx.x & 31;
    const int d = w % NN;
    const int chunk = w / NN;
    const int c = chunk * 256 + lane * 8;
    const int h = (chunk * 256) >> cshift;      // warp-uniform head
    const int r0 = rowptr[d], r1 = rowptr[d + 1];
    float acc[8];
    #pragma unroll
    for (int q = 0; q < 8; q++) acc[q] = 0.f;

    for (int e0 = r0; e0 < r1; e0 += 32) {
        int e = e0 + lane;
        int mys = 0; float mya = 0.f;
        if (e < r1) {
            mys = src[e];
            mya = alpha[(size_t)e * H + h];
        }
        int cnt = min(32, r1 - e0);
        int j = 0;
        for (; j + 3 < cnt; j += 4) {
            int s0 = __shfl_sync(0xFFFFFFFFu, mys, j);
            int s1 = __shfl_sync(0xFFFFFFFFu, mys, j + 1);
            int s2 = __shfl_sync(0xFFFFFFFFu, mys, j + 2);
            int s3 = __shfl_sync(0xFFFFFFFFu, mys, j + 3);
            float a0 = __shfl_sync(0xFFFFFFFFu, mya, j);
            float a1 = __shfl_sync(0xFFFFFFFFu, mya, j + 1);
            float a2 = __shfl_sync(0xFFFFFFFFu, mya, j + 2);
            float a3 = __shfl_sync(0xFFFFFFFFu, mya, j + 3);
            uint4 r0v = *(const uint4*)(hlin + (size_t)s0 * HC + c);
            uint4 r1v = *(const uint4*)(hlin + (size_t)s1 * HC + c);
            uint4 r2v = *(const uint4*)(hlin + (size_t)s2 * HC + c);
            uint4 r3v = *(const uint4*)(hlin + (size_t)s3 * HC + c);
            const __half2* h0 = (const __half2*)&r0v;
            const __half2* h1 = (const __half2*)&r1v;
            const __half2* h2 = (const __half2*)&r2v;
            const __half2* h3 = (const __half2*)&r3v;
            #pragma unroll
            for (int q = 0; q < 4; q++) {
                float2 f0 = __half22float2(h0[q]);
                float2 f1 = __half22float2(h1[q]);
                float2 f2 = __half22float2(h2[q]);
                float2 f3 = __half22float2(h3[q]);
                acc[q * 2 + 0] = fmaf(a0, f0.x, fmaf(a1, f1.x,
                                 fmaf(a2, f2.x, fmaf(a3, f3.x, acc[q * 2 + 0]))));
                acc[q * 2 + 1] = fmaf(a0, f0.y, fmaf(a1, f1.y,
                                 fmaf(a2, f2.y, fmaf(a3, f3.y, acc[q * 2 + 1]))));
            }
        }
        for (; j < cnt; j++) {
            int s0 = __shfl_sync(0xFFFFFFFFu, mys, j);
            float a0 = __shfl_sync(0xFFFFFFFFu, mya, j);
            uint4 raw = *(const uint4*)(hlin + (size_t)s0 * HC + c);
            const __half2* hp = (const __half2*)&raw;
            #pragma unroll
            for (int q = 0; q < 4; q++) {
                float2 f = __half22float2(hp[q]);
                acc[q * 2 + 0] = fmaf(a0, f.x, acc[q * 2 + 0]);
                acc[q * 2 + 1] = fmaf(a0, f.y, acc[q * 2 + 1]);
            }
        }
    }

    __half2 hx[4];
    #pragma unroll
    for (int q = 0; q < 4; q++) {
        float v0 = lrelu(acc[q * 2 + 0] + bias[c + q * 2 + 0]);
        float v1 = lrelu(acc[q * 2 + 1] + bias[c + q * 2 + 1]);
        hx[q] = __floats2half2_rn(v0, v1);
    }
    *(uint4*)(outA + (size_t)d * HC + c) = *(uint4*)hx;
}

// ---------------- pooling (sorted-batch run accumulation, fp16 input) -------
__global__ void pool2(const __half* __restrict__ h, const int* __restrict__ batch,
                      float* __restrict__ pool, float* __restrict__ cnt) {
    __shared__ int bid[128];
    int base = blockIdx.x * 128;
    int tid = threadIdx.x;
    for (int i = tid; i < 128; i += 256)
        bid[i] = (base + i < NN) ? batch[base + i] : -1;
    __syncthreads();
    int c = tid;
    float a0 = 0.f, a1 = 0.f;
    int rl = 0;
    int cur = bid[0];
    for (int i = 0; i < 128; i++) {
        int g = bid[i];
        if (g < 0) break;
        if (g != cur) {
            atomicAdd(&pool[cur * FEAT + c], a0);
            atomicAdd(&pool[cur * FEAT + c + 256], a1);
            if (tid == 0) atomicAdd(&cnt[cur], (float)rl);
            a0 = a1 = 0.f;
            rl = 0;
            cur = g;
        }
        const __half* row = h + (size_t)(base + i) * FEAT;
        a0 += __half2float(row[c]);
        a1 += __half2float(row[c + 256]);
        rl++;
    }
    if (cur >= 0) {
        atomicAdd(&pool[cur * FEAT + c], a0);
        atomicAdd(&pool[cur * FEAT + c + 256], a1);
        if (tid == 0) atomicAdd(&cnt[cur], (float)rl);
    }
}

__global__ void final_mlp(const float* __restrict__ pool, const float* __restrict__ cnt,
                          const float* __restrict__ Wf, const float* __restrict__ bf,
                          float* __restrict__ out)
{
    int g = blockIdx.x;
    int o = threadIdx.x;
    float inv = 1.0f / fmaxf(cnt[g], 1.0f);
    float acc = bf[o];
    const float* pg = pool + g * FEAT;
    #pragma unroll 8
    for (int k = 0; k < FEAT; k++)
        acc = fmaf(pg[k] * inv, Wf[k * FEAT + o], acc);
    out[g * FEAT + o] = lrelu(acc);
}

// ---------------- host orchestration ----------------------------------------
struct Ptrs {
    float *scores, *alpha, *pool, *cnt;
    __half *hout, *hlin, *A, *B;
    int *rowptr, *deg, *cursor, *src;
};

extern "C" void kernel_launch(void* const* d_in, const int* in_sizes, int n_in,
                              void* d_out, int out_size)
{
    const float* x     = (const float*)d_in[0];
    const int*   ei    = (const int*)  d_in[1];
    const int*   batch = (const int*)  d_in[2];
    const float* W0  = (const float*)d_in[3];
    const float* b0  = (const float*)d_in[4];
    const float* W1  = (const float*)d_in[5];
    const float* a1s = (const float*)d_in[6];
    const float* a1d = (const float*)d_in[7];
    const float* b1  = (const float*)d_in[8];
    const float* W2  = (const float*)d_in[9];
    const float* a2s = (const float*)d_in[10];
    const float* a2d = (const float*)d_in[11];
    const float* b2  = (const float*)d_in[12];
    const float* W3  = (const float*)d_in[13];
    const float* a3s = (const float*)d_in[14];
    const float* a3d = (const float*)d_in[15];
    const float* b3  = (const float*)d_in[16];
    const float* Wf  = (const float*)d_in[17];
    const float* bf  = (const float*)d_in[18];
    float* out = (float*)d_out;

    cudaFuncSetAttribute(wgemm, cudaFuncAttributeMaxDynamicSharedMemorySize, WG_SMEM);

    Ptrs P;
    cudaGetSymbolAddress((void**)&P.hout,   g_hout);
    cudaGetSymbolAddress((void**)&P.hlin,   g_hlin);
    cudaGetSymbolAddress((void**)&P.scores, g_scores);
    cudaGetSymbolAddress((void**)&P.alpha,  g_alpha);
    cudaGetSymbolAddress((void**)&P.pool,   g_pool);
    cudaGetSymbolAddress((void**)&P.cnt,    g_cnt);
    cudaGetSymbolAddress((void**)&P.A,      g_A);
    cudaGetSymbolAddress((void**)&P.B,      g_B);
    cudaGetSymbolAddress((void**)&P.rowptr, g_rowptr);
    cudaGetSymbolAddress((void**)&P.deg,    g_deg);
    cudaGetSymbolAddress((void**)&P.cursor, g_cursor);
    cudaGetSymbolAddress((void**)&P.src,    g_src);

    float* esrc = P.scores;
    float* edst = P.scores + NN * HEADS;

    const float* Ws[3]  = { W1, W2, W3 };
    const float* ass[3] = { a1s, a2s, a3s };
    const float* ads[3] = { a1d, a2d, a3d };
    const float* bs[3]  = { b1, b2, b3 };
    const int Kin[3]    = { EMB, HC1, HC1 };
    const int Hs[3]     = { HEADS, HEADS, 1 };
    const int Cs[3]     = { HID, HID, OUTC };
    const int cshifts[3]= { 8, 8, 9 };

    // 1: layer0 GEMM (writes fp16 A directly)
    {
        dim3 g0(EMB / 128, (NN + 127) / 128);
        sgemm0<<<g0, 256>>>(x, W0, P.A, NN, EMB, TILE_, b0);
    }
    // 2: weight convert for layer 1
    {
        dim3 tb(32, 8), tg(HC1 / 32, EMB / 32);
        tconv_t<<<tg, tb>>>(W1, P.B, EMB, HC1);
    }
    // 3: zero scores
    fillk<<<64, 256>>>(P.scores, 0.f, (size_t)2 * NN * HEADS);
    // 4: wgemm layer 1  <-- ncu capture slot
    {
        dim3 gg(HC1 / 128, (NN + 127) / 128);
        wgemm<<<gg, 256, WG_SMEM>>>(P.A, P.B, P.hlin, NN, HC1, EMB,
                                    a1s, a1d, esrc, edst, HEADS, HID);
    }
    // CSR build
    filli<<<(NN + 255) / 256, 256>>>(P.deg, 0, NN);
    count_deg<<<(ET + 255) / 256, 256>>>(ei, P.deg);
    scan_rowptr<<<1, 1024>>>(P.deg, P.rowptr, P.cursor);
    scatter_edges<<<(ET + 255) / 256, 256>>>(ei, P.cursor, P.src);

    for (int L = 0; L < 3; L++) {
        int H = Hs[L], C = Cs[L], HC = H * C;
        if (L > 0) {
            dim3 tb(32, 8), tg(HC / 32, Kin[L] / 32);
            tconv_t<<<tg, tb>>>(Ws[L], P.B, Kin[L], HC);
            fillk<<<64, 256>>>(P.scores, 0.f, (size_t)2 * NN * HEADS);
            dim3 gg(HC / 128, (NN + 127) / 128);
            wgemm<<<gg, 256, WG_SMEM>>>(P.A, P.B, P.hlin, NN, HC, Kin[L],
                                        ass[L], ads[L], esrc, edst, H, C);
        }
        gat_alpha<<<(NN * 32 + 255) / 256, 256>>>(P.rowptr, P.src, esrc, edst,
                                                  P.alpha, H);
        int nchunks = HC / 256;
        int nwarps = NN * nchunks;
        __half* dstA = (L == 2) ? P.hout : P.A;
        gat_gather<<<nwarps / 8, 256>>>(P.rowptr, P.src, P.hlin, P.alpha,
                                        bs[L], dstA, H, HC, cshifts[L]);
    }

    // ---- global mean pool + final MLP ----
    fillk<<<32, 256>>>(P.pool, 0.f, (size_t)GG * FEAT);
    fillk<<<1, 32>>>(P.cnt, 0.f, (size_t)GG);
    pool2<<<(NN + 127) / 128, 256>>>(P.hout, batch, P.pool, P.cnt);
    final_mlp<<<GG, FEAT>>>(P.pool, P.cnt, Wf, bf, out);
}